// round 1
// baseline (speedup 1.0000x reference)
#include <cuda_runtime.h>
#include <math.h>
#include <stdint.h>

// Problem constants
#define BB 16
#define NN 2048
#define CC 768
#define NTOK (BB*NN)          // 32768
#define LN_EPS 1e-5f
#define RSQRT_C 0.03608439182435161f   // 1/sqrt(768)

// ---------------- scratch (device globals; no runtime alloc allowed) ----------
__device__ float g_y[(size_t)NTOK * CC];           // conv output, then LN output (in place)
__device__ float g_dist[(size_t)NTOK * NN];        // 268 MB distance matrix
__device__ float g_wt[3 * CC * CC];                // repacked conv weight [k][ci][co]
__device__ float g_sq[NTOK];
__device__ float g_tw[NTOK];
__device__ float g_density[NTOK];
__device__ float g_score[NTOK];
__device__ float g_distmax[BB];
__device__ int   g_idxdown[BB * 2];
__device__ float g_allw[BB * 2];
__device__ int   g_cluster[NTOK];

// ---------------- small helpers ------------------------------------------------
__global__ void repack_kernel(const float* __restrict__ w) {
    int i = blockIdx.x * 256 + threadIdx.x;     // over 768*768*3, w is [co][ci][k]
    if (i >= CC * CC * 3) return;
    int k  = i % 3;
    int ci = (i / 3) % CC;
    int co = i / (3 * CC);
    g_wt[((size_t)k * CC + ci) * CC + co] = w[i];
}

__global__ void init_kernel() {
    int t = threadIdx.x;
    if (t < BB) g_distmax[t] = 0.0f;
    if (t < BB * 2) g_allw[t] = 1e-6f;
}

// ---------------- GEMM 1: residual conv  y = x + sum_k X_shift(k) @ Wk ---------
// M=32768, N=768, K=2304 (3 shifts * 768). 128x128x8 double-buffered SGEMM.
__global__ __launch_bounds__(256) void conv_gemm_kernel(const float* __restrict__ x) {
    __shared__ float As[2][8][128];
    __shared__ float Bs[2][8][128];
    const int tid = threadIdx.x;
    const int co0 = blockIdx.x * 128;   // 0..5
    const int m0  = blockIdx.y * 128;   // 0..255

    const int arow = tid >> 1;            // 0..127
    const int acol = (tid & 1) << 2;      // 0 / 4
    const int brow = tid >> 5;            // 0..7
    const int bcol = (tid & 31) << 2;     // 0..124
    const int ty = tid >> 4, tx = tid & 15;

    const int m  = m0 + arow;
    const int bb = m >> 11;
    const int nn = m & 2047;

    float acc[8][8];
#pragma unroll
    for (int i = 0; i < 8; ++i)
#pragma unroll
        for (int j = 0; j < 8; ++j) acc[i][j] = 0.f;

    float4 a, b4;
    // chunk 0: kk=0 -> source row nn-1
    {
        int r = nn - 1;
        if (r >= 0)
            a = *reinterpret_cast<const float4*>(x + ((size_t)(bb * NN + r)) * CC + acol);
        else
            a = make_float4(0.f, 0.f, 0.f, 0.f);
        b4 = *reinterpret_cast<const float4*>(g_wt + (size_t)brow * CC + co0 + bcol);
    }
    int buf = 0;
    As[buf][acol + 0][arow] = a.x; As[buf][acol + 1][arow] = a.y;
    As[buf][acol + 2][arow] = a.z; As[buf][acol + 3][arow] = a.w;
    *reinterpret_cast<float4*>(&Bs[buf][brow][bcol]) = b4;
    __syncthreads();

    const int T = 288;   // 3*768/8
    for (int t = 0; t < T; ++t) {
        if (t + 1 < T) {
            int tn = t + 1;
            int kk = tn / 96;
            int ci = (tn - kk * 96) * 8 + acol;
            int r  = nn + kk - 1;
            if (r >= 0 && r < NN)
                a = *reinterpret_cast<const float4*>(x + ((size_t)(bb * NN + r)) * CC + ci);
            else
                a = make_float4(0.f, 0.f, 0.f, 0.f);
            b4 = *reinterpret_cast<const float4*>(g_wt + ((size_t)tn * 8 + brow) * CC + co0 + bcol);
        }
#pragma unroll
        for (int k = 0; k < 8; ++k) {
            float af[8], bf[8];
            *reinterpret_cast<float4*>(af)     = *reinterpret_cast<const float4*>(&As[buf][k][ty * 4]);
            *reinterpret_cast<float4*>(af + 4) = *reinterpret_cast<const float4*>(&As[buf][k][64 + ty * 4]);
            *reinterpret_cast<float4*>(bf)     = *reinterpret_cast<const float4*>(&Bs[buf][k][tx * 4]);
            *reinterpret_cast<float4*>(bf + 4) = *reinterpret_cast<const float4*>(&Bs[buf][k][64 + tx * 4]);
#pragma unroll
            for (int i = 0; i < 8; ++i)
#pragma unroll
                for (int j = 0; j < 8; ++j) acc[i][j] = fmaf(af[i], bf[j], acc[i][j]);
        }
        if (t + 1 < T) {
            buf ^= 1;
            As[buf][acol + 0][arow] = a.x; As[buf][acol + 1][arow] = a.y;
            As[buf][acol + 2][arow] = a.z; As[buf][acol + 3][arow] = a.w;
            *reinterpret_cast<float4*>(&Bs[buf][brow][bcol]) = b4;
            __syncthreads();
        }
    }

    // epilogue: y = x + acc (residual)
#pragma unroll
    for (int ih = 0; ih < 2; ++ih) {
#pragma unroll
        for (int ii = 0; ii < 4; ++ii) {
            int row = m0 + ih * 64 + ty * 4 + ii;
            size_t base = (size_t)row * CC;
#pragma unroll
            for (int jh = 0; jh < 2; ++jh) {
                int col = co0 + jh * 64 + tx * 4;
                float4 xv = *reinterpret_cast<const float4*>(x + base + col);
                float4 o;
                o.x = xv.x + acc[ih * 4 + ii][jh * 4 + 0];
                o.y = xv.y + acc[ih * 4 + ii][jh * 4 + 1];
                o.z = xv.z + acc[ih * 4 + ii][jh * 4 + 2];
                o.w = xv.w + acc[ih * 4 + ii][jh * 4 + 3];
                *reinterpret_cast<float4*>(g_y + base + col) = o;
            }
        }
    }
}

// ---------------- LayerNorm + score + sq (block per row) -----------------------
__global__ __launch_bounds__(256) void ln_kernel(const float* __restrict__ gamma,
                                                 const float* __restrict__ beta,
                                                 const float* __restrict__ sw,
                                                 const float* __restrict__ sb) {
    __shared__ float red[256];
    const int m = blockIdx.x;
    const int tid = threadIdx.x;
    float* yrow = g_y + (size_t)m * CC;

    float v0 = yrow[tid], v1 = yrow[tid + 256], v2 = yrow[tid + 512];

    // mean
    red[tid] = v0 + v1 + v2; __syncthreads();
    for (int o = 128; o; o >>= 1) { if (tid < o) red[tid] += red[tid + o]; __syncthreads(); }
    float mu = red[0] / (float)CC;
    __syncthreads();

    float d0 = v0 - mu, d1 = v1 - mu, d2 = v2 - mu;
    red[tid] = d0 * d0 + d1 * d1 + d2 * d2; __syncthreads();
    for (int o = 128; o; o >>= 1) { if (tid < o) red[tid] += red[tid + o]; __syncthreads(); }
    float var = red[0] / (float)CC;
    float inv = 1.0f / sqrtf(var + LN_EPS);
    __syncthreads();

    float x0 = d0 * inv * gamma[tid]       + beta[tid];
    float x1 = d1 * inv * gamma[tid + 256] + beta[tid + 256];
    float x2 = d2 * inv * gamma[tid + 512] + beta[tid + 512];
    yrow[tid] = x0; yrow[tid + 256] = x1; yrow[tid + 512] = x2;

    // sq = sum(x^2)
    red[tid] = x0 * x0 + x1 * x1 + x2 * x2; __syncthreads();
    for (int o = 128; o; o >>= 1) { if (tid < o) red[tid] += red[tid + o]; __syncthreads(); }
    float sqv = red[0];
    __syncthreads();

    // score
    red[tid] = x0 * sw[tid] + x1 * sw[tid + 256] + x2 * sw[tid + 512]; __syncthreads();
    for (int o = 128; o; o >>= 1) { if (tid < o) red[tid] += red[tid + o]; __syncthreads(); }
    if (tid == 0) {
        g_sq[m] = sqv;
        g_tw[m] = expf(red[0] + sb[0]);
    }
}

// ---------------- GEMM 2: Gram + dist epilogue (per batch A·Aᵀ) ----------------
__global__ __launch_bounds__(256) void gram_kernel() {
    __shared__ float As[2][8][128];
    __shared__ float Bs[2][8][128];
    const int tid = threadIdx.x;
    const int b  = blockIdx.z;
    const int j0 = blockIdx.x * 128;
    const int i0 = blockIdx.y * 128;
    const float* xb = g_y + (size_t)b * NN * CC;

    const int lrow = tid >> 1;
    const int lcol = (tid & 1) << 2;
    const int ty = tid >> 4, tx = tid & 15;

    const float* aPtr = xb + (size_t)(i0 + lrow) * CC + lcol;
    const float* bPtr = xb + (size_t)(j0 + lrow) * CC + lcol;

    float acc[8][8];
#pragma unroll
    for (int i = 0; i < 8; ++i)
#pragma unroll
        for (int j = 0; j < 8; ++j) acc[i][j] = 0.f;

    float4 a  = *reinterpret_cast<const float4*>(aPtr);
    float4 b4 = *reinterpret_cast<const float4*>(bPtr);
    int buf = 0;
    As[buf][lcol + 0][lrow] = a.x;  As[buf][lcol + 1][lrow] = a.y;
    As[buf][lcol + 2][lrow] = a.z;  As[buf][lcol + 3][lrow] = a.w;
    Bs[buf][lcol + 0][lrow] = b4.x; Bs[buf][lcol + 1][lrow] = b4.y;
    Bs[buf][lcol + 2][lrow] = b4.z; Bs[buf][lcol + 3][lrow] = b4.w;
    __syncthreads();

    const int T = 96;   // 768/8
    for (int t = 0; t < T; ++t) {
        if (t + 1 < T) {
            a  = *reinterpret_cast<const float4*>(aPtr + (t + 1) * 8);
            b4 = *reinterpret_cast<const float4*>(bPtr + (t + 1) * 8);
        }
#pragma unroll
        for (int k = 0; k < 8; ++k) {
            float af[8], bf[8];
            *reinterpret_cast<float4*>(af)     = *reinterpret_cast<const float4*>(&As[buf][k][ty * 4]);
            *reinterpret_cast<float4*>(af + 4) = *reinterpret_cast<const float4*>(&As[buf][k][64 + ty * 4]);
            *reinterpret_cast<float4*>(bf)     = *reinterpret_cast<const float4*>(&Bs[buf][k][tx * 4]);
            *reinterpret_cast<float4*>(bf + 4) = *reinterpret_cast<const float4*>(&Bs[buf][k][64 + tx * 4]);
#pragma unroll
            for (int i = 0; i < 8; ++i)
#pragma unroll
                for (int j = 0; j < 8; ++j) acc[i][j] = fmaf(af[i], bf[j], acc[i][j]);
        }
        if (t + 1 < T) {
            buf ^= 1;
            As[buf][lcol + 0][lrow] = a.x;  As[buf][lcol + 1][lrow] = a.y;
            As[buf][lcol + 2][lrow] = a.z;  As[buf][lcol + 3][lrow] = a.w;
            Bs[buf][lcol + 0][lrow] = b4.x; Bs[buf][lcol + 1][lrow] = b4.y;
            Bs[buf][lcol + 2][lrow] = b4.z; Bs[buf][lcol + 3][lrow] = b4.w;
            __syncthreads();
        }
    }

    const float* sqb = g_sq + b * NN;
    float sqi[8], sqj[8];
#pragma unroll
    for (int ih = 0; ih < 2; ++ih)
#pragma unroll
        for (int ii = 0; ii < 4; ++ii) sqi[ih * 4 + ii] = sqb[i0 + ih * 64 + ty * 4 + ii];
#pragma unroll
    for (int jh = 0; jh < 2; ++jh)
#pragma unroll
        for (int jj = 0; jj < 4; ++jj) sqj[jh * 4 + jj] = sqb[j0 + jh * 64 + tx * 4 + jj];

#pragma unroll
    for (int ih = 0; ih < 2; ++ih) {
#pragma unroll
        for (int ii = 0; ii < 4; ++ii) {
            int i = i0 + ih * 64 + ty * 4 + ii;
            float* drow = g_dist + ((size_t)(b * NN + i)) * NN;
#pragma unroll
            for (int jh = 0; jh < 2; ++jh) {
                float4 o;
                float d;
                d = (sqi[ih*4+ii] + sqj[jh*4+0]) - 2.0f * acc[ih*4+ii][jh*4+0];
                o.x = sqrtf(fmaxf(d, 0.f)) * RSQRT_C;
                d = (sqi[ih*4+ii] + sqj[jh*4+1]) - 2.0f * acc[ih*4+ii][jh*4+1];
                o.y = sqrtf(fmaxf(d, 0.f)) * RSQRT_C;
                d = (sqi[ih*4+ii] + sqj[jh*4+2]) - 2.0f * acc[ih*4+ii][jh*4+2];
                o.z = sqrtf(fmaxf(d, 0.f)) * RSQRT_C;
                d = (sqi[ih*4+ii] + sqj[jh*4+3]) - 2.0f * acc[ih*4+ii][jh*4+3];
                o.w = sqrtf(fmaxf(d, 0.f)) * RSQRT_C;
                *reinterpret_cast<float4*>(drow + j0 + jh * 64 + tx * 4) = o;
            }
        }
    }
}

// ---------------- top-3 smallest per row -> density; row max -> dist_max -------
__global__ __launch_bounds__(256) void knn_kernel(const float* __restrict__ noise) {
    const int m = blockIdx.x;
    const int b = m >> 11;
    const float* drow = g_dist + (size_t)m * NN;
    const int tid = threadIdx.x;

    float t0 = 1e30f, t1 = 1e30f, t2 = 1e30f, mx = 0.f;
    for (int j = tid; j < NN; j += 256) {
        float v = drow[j];
        mx = fmaxf(mx, v);
        if (v < t2) {
            if (v < t1) { t2 = t1; if (v < t0) { t1 = t0; t0 = v; } else t1 = v; }
            else t2 = v;
        }
    }
#pragma unroll
    for (int o = 16; o > 0; o >>= 1) {
        float u0 = __shfl_down_sync(0xffffffffu, t0, o);
        float u1 = __shfl_down_sync(0xffffffffu, t1, o);
        float u2 = __shfl_down_sync(0xffffffffu, t2, o);
        float um = __shfl_down_sync(0xffffffffu, mx, o);
        mx = fmaxf(mx, um);
        if (u0 < t2) { if (u0 < t1) { t2 = t1; if (u0 < t0) { t1 = t0; t0 = u0; } else t1 = u0; } else t2 = u0; }
        if (u1 < t2) { if (u1 < t1) { t2 = t1; if (u1 < t0) { t1 = t0; t0 = u1; } else t1 = u1; } else t2 = u1; }
        if (u2 < t2) { if (u2 < t1) { t2 = t1; if (u2 < t0) { t1 = t0; t0 = u2; } else t1 = u2; } else t2 = u2; }
    }
    __shared__ float s0[8], s1[8], s2[8], smx[8];
    int wid = tid >> 5, lane = tid & 31;
    if (lane == 0) { s0[wid] = t0; s1[wid] = t1; s2[wid] = t2; smx[wid] = mx; }
    __syncthreads();
    if (tid < 32) {
        t0 = (tid < 8) ? s0[tid] : 1e30f;
        t1 = (tid < 8) ? s1[tid] : 1e30f;
        t2 = (tid < 8) ? s2[tid] : 1e30f;
        mx = (tid < 8) ? smx[tid] : 0.f;
#pragma unroll
        for (int o = 4; o > 0; o >>= 1) {
            float u0 = __shfl_down_sync(0xffffffffu, t0, o);
            float u1 = __shfl_down_sync(0xffffffffu, t1, o);
            float u2 = __shfl_down_sync(0xffffffffu, t2, o);
            float um = __shfl_down_sync(0xffffffffu, mx, o);
            mx = fmaxf(mx, um);
            if (u0 < t2) { if (u0 < t1) { t2 = t1; if (u0 < t0) { t1 = t0; t0 = u0; } else t1 = u0; } else t2 = u0; }
            if (u1 < t2) { if (u1 < t1) { t2 = t1; if (u1 < t0) { t1 = t0; t0 = u1; } else t1 = u1; } else t2 = u1; }
            if (u2 < t2) { if (u2 < t1) { t2 = t1; if (u2 < t0) { t1 = t0; t0 = u2; } else t1 = u2; } else t2 = u2; }
        }
        if (tid == 0) {
            float ds = (t0 * t0 + t1 * t1 + t2 * t2) / 3.0f;
            g_density[m] = expf(-ds) + noise[m] * 1e-6f;
            atomicMax((int*)(g_distmax + b), __float_as_int(mx));   // dist >= 0
        }
    }
}

// ---------------- dist_min to higher-density point; score ----------------------
__global__ __launch_bounds__(256) void distmin_kernel() {
    __shared__ float dens[NN];
    __shared__ float red[256];
    const int m = blockIdx.x;
    const int b = m >> 11;
    const int tid = threadIdx.x;
    const float* db = g_density + b * NN;
    for (int j = tid; j < NN; j += 256) dens[j] = db[j];
    __syncthreads();

    const float di   = dens[m & 2047];
    const float dmax = g_distmax[b];
    const float* drow = g_dist + (size_t)m * NN;

    float mn = dmax;
    for (int j = tid; j < NN; j += 256) {
        float c = (dens[j] > di) ? drow[j] : dmax;
        mn = fminf(mn, c);
    }
    red[tid] = mn; __syncthreads();
    for (int o = 128; o; o >>= 1) { if (tid < o) red[tid] = fminf(red[tid], red[tid + o]); __syncthreads(); }
    if (tid == 0) g_score[m] = red[0] * di;
}

// ---------------- per-batch top-2 of score (lax.top_k tie: lower index) --------
__global__ __launch_bounds__(256) void top2_kernel() {
    __shared__ float sv[256];
    __shared__ int   si[256];
    const int b = blockIdx.x, tid = threadIdx.x;
    const float* sc = g_score + b * NN;

    float bv = -1e30f; int bi = 1 << 30;
    for (int j = tid; j < NN; j += 256) {
        float v = sc[j];
        if (v > bv || (v == bv && j < bi)) { bv = v; bi = j; }
    }
    sv[tid] = bv; si[tid] = bi; __syncthreads();
    for (int o = 128; o; o >>= 1) {
        if (tid < o) {
            float ov = sv[tid + o]; int oi = si[tid + o];
            if (ov > sv[tid] || (ov == sv[tid] && oi < si[tid])) { sv[tid] = ov; si[tid] = oi; }
        }
        __syncthreads();
    }
    int i0 = si[0];
    __syncthreads();

    bv = -1e30f; bi = 1 << 30;
    for (int j = tid; j < NN; j += 256) {
        if (j == i0) continue;
        float v = sc[j];
        if (v > bv || (v == bv && j < bi)) { bv = v; bi = j; }
    }
    sv[tid] = bv; si[tid] = bi; __syncthreads();
    for (int o = 128; o; o >>= 1) {
        if (tid < o) {
            float ov = sv[tid + o]; int oi = si[tid + o];
            if (ov > sv[tid] || (ov == sv[tid] && oi < si[tid])) { sv[tid] = ov; si[tid] = oi; }
        }
        __syncthreads();
    }
    if (tid == 0) { g_idxdown[b * 2] = i0; g_idxdown[b * 2 + 1] = si[0]; }
}

// ---------------- cluster assignment + all_weight accumulation ------------------
__global__ void assign_kernel(float* __restrict__ out) {
    int m = blockIdx.x * 256 + threadIdx.x;
    if (m >= NTOK) return;
    int b = m >> 11, n = m & 2047;
    int i0 = g_idxdown[b * 2], i1 = g_idxdown[b * 2 + 1];
    float d0 = g_dist[((size_t)(b * NN + i0)) * NN + n];
    float d1 = g_dist[((size_t)(b * NN + i1)) * NN + n];
    int cl = (d0 <= d1) ? 0 : 1;   // argmin tie -> first
    if (n == i0) cl = 0;
    if (n == i1) cl = 1;
    g_cluster[m] = cl;
    out[24576 + 32768 + m] = (float)cl;        // idx_cluster region (as float)
    atomicAdd(&g_allw[b * 2 + cl], g_tw[m]);
}

// ---------------- normalized weight output --------------------------------------
__global__ void weight_kernel(float* __restrict__ out) {
    int m = blockIdx.x * 256 + threadIdx.x;
    if (m >= NTOK) return;
    int b = m >> 11;
    float nw = g_tw[m] / g_allw[b * 2 + g_cluster[m]];
    out[24576 + m] = nw;                        // agg_weight_new region
}

// ---------------- weighted merge x_merged[b,k,:] ---------------------------------
__global__ __launch_bounds__(256) void merge_kernel(float* __restrict__ out) {
    __shared__ float wgt[NN];
    const int k = blockIdx.y, b = blockIdx.z;
    const int tid = threadIdx.x;
    const int c = blockIdx.x * 256 + tid;
    const float aw = g_allw[b * 2 + k];
    const int*   cl = g_cluster + b * NN;
    const float* tw = g_tw + b * NN;
    for (int j = tid; j < NN; j += 256)
        wgt[j] = (cl[j] == k) ? (tw[j] / aw) : 0.0f;
    __syncthreads();
    const float* xb = g_y + (size_t)b * NN * CC;
    float acc = 0.f;
    for (int n = 0; n < NN; ++n)
        acc = fmaf(xb[(size_t)n * CC + c], wgt[n], acc);
    out[(size_t)(b * 2 + k) * CC + c] = acc;    // x_merged region
}

// ---------------- launch --------------------------------------------------------
extern "C" void kernel_launch(void* const* d_in, const int* in_sizes, int n_in,
                              void* d_out, int out_size) {
    const float* x      = (const float*)d_in[0];
    const float* conv_w = (const float*)d_in[1];
    const float* gamma  = (const float*)d_in[2];
    const float* beta   = (const float*)d_in[3];
    const float* sw     = (const float*)d_in[4];
    const float* sb     = (const float*)d_in[5];
    const float* noise  = (const float*)d_in[6];
    float* out = (float*)d_out;

    repack_kernel<<<(CC * CC * 3 + 255) / 256, 256>>>(conv_w);
    init_kernel<<<1, 32>>>();
    conv_gemm_kernel<<<dim3(CC / 128, NTOK / 128), 256>>>(x);
    ln_kernel<<<NTOK, 256>>>(gamma, beta, sw, sb);
    gram_kernel<<<dim3(NN / 128, NN / 128, BB), 256>>>();
    knn_kernel<<<NTOK, 256>>>(noise);
    distmin_kernel<<<NTOK, 256>>>();
    top2_kernel<<<BB, 256>>>();
    assign_kernel<<<NTOK / 256, 256>>>(out);
    weight_kernel<<<NTOK / 256, 256>>>(out);
    merge_kernel<<<dim3(CC / 256, 2, BB), 256>>>(out);
}

// round 7
// speedup vs baseline: 1.1006x; 1.1006x over previous
#include <cuda_runtime.h>
#include <math.h>
#include <stdint.h>

// Problem constants
#define BB 16
#define NN 2048
#define CC 768
#define NTOK (BB*NN)          // 32768
#define LN_EPS 1e-5f
#define RSQRT_C 0.03608439182435161f   // 1/sqrt(768)

// GEMM tiling: CTA 128(m) x 256(n) x 16(k), 8 warps of 64x64
#define ROWPAD 20                      // floats per smem row (16 + 4 pad)
#define A_HI 0
#define A_LO (128*ROWPAD)              // 2560
#define B_HI (2*128*ROWPAD)            // 5120
#define B_LO (B_HI + 256*ROWPAD)       // 10240
#define BUF_F (B_LO + 256*ROWPAD)      // 15360 floats per stage
#define SMEM_BYTES (2*BUF_F*4)         // 122880

// ---------------- scratch (device globals; no runtime alloc allowed) ----------
__device__ float g_y[(size_t)NTOK * CC];           // conv+LN output
__device__ float g_dist[(size_t)NTOK * NN];        // 268 MB distance matrix
__device__ float g_wt[3 * CC * CC];                // repacked conv weight [k][co][ci]
__device__ float g_sq[NTOK];
__device__ float g_tw[NTOK];
__device__ float g_density[NTOK];
__device__ float g_score[NTOK];
__device__ float g_distmax[BB];
__device__ int   g_idxdown[BB * 2];
__device__ float g_allw[BB * 2];
__device__ int   g_cluster[NTOK];

// ---------------- helpers -------------------------------------------------------
__device__ __forceinline__ float tf32r(float x) {
    uint32_t u; asm("cvt.rna.tf32.f32 %0, %1;" : "=r"(u) : "f"(x));
    return __uint_as_float(u);
}

__device__ __forceinline__ void mma8(float* d, const uint32_t* a, uint32_t b0, uint32_t b1) {
    asm volatile(
        "mma.sync.aligned.m16n8k8.row.col.f32.tf32.tf32.f32 "
        "{%0,%1,%2,%3},{%4,%5,%6,%7},{%8,%9},{%0,%1,%2,%3};"
        : "+f"(d[0]), "+f"(d[1]), "+f"(d[2]), "+f"(d[3])
        : "r"(a[0]), "r"(a[1]), "r"(a[2]), "r"(a[3]), "r"(b0), "r"(b1));
}

__device__ __forceinline__ void split_store(float* hi, float* lo, int row, int c4, float4 v) {
    float4 h, l;
    h.x = tf32r(v.x); h.y = tf32r(v.y); h.z = tf32r(v.z); h.w = tf32r(v.w);
    l.x = tf32r(v.x - h.x); l.y = tf32r(v.y - h.y);
    l.z = tf32r(v.z - h.z); l.w = tf32r(v.w - h.w);
    *reinterpret_cast<float4*>(hi + row * ROWPAD + c4 * 4) = h;
    *reinterpret_cast<float4*>(lo + row * ROWPAD + c4 * 4) = l;
}

// Warp-level 3xTF32 compute for one k16 stage (two k8 groups)
__device__ __forceinline__ void mma_compute(const float* buf, float acc[4][8][4],
                                            int w, int lane) {
    const uint32_t* sa_hi = reinterpret_cast<const uint32_t*>(buf + A_HI);
    const uint32_t* sa_lo = reinterpret_cast<const uint32_t*>(buf + A_LO);
    const uint32_t* sb_hi = reinterpret_cast<const uint32_t*>(buf + B_HI);
    const uint32_t* sb_lo = reinterpret_cast<const uint32_t*>(buf + B_LO);
    const int mb = (w >> 2) * 64 + (lane >> 2);
    const int nb = (w & 3) * 64 + (lane >> 2);
    const int kc = lane & 3;
#pragma unroll
    for (int g = 0; g < 2; ++g) {
        uint32_t Ah[4][4], Al[4][4];
#pragma unroll
        for (int mi = 0; mi < 4; ++mi) {
            int off = (mb + mi * 16) * ROWPAD + g * 8 + kc;
            Ah[mi][0] = sa_hi[off];                 Ah[mi][1] = sa_hi[off + 8 * ROWPAD];
            Ah[mi][2] = sa_hi[off + 4];             Ah[mi][3] = sa_hi[off + 8 * ROWPAD + 4];
            Al[mi][0] = sa_lo[off];                 Al[mi][1] = sa_lo[off + 8 * ROWPAD];
            Al[mi][2] = sa_lo[off + 4];             Al[mi][3] = sa_lo[off + 8 * ROWPAD + 4];
        }
#pragma unroll
        for (int ni = 0; ni < 8; ++ni) {
            int off = (nb + ni * 8) * ROWPAD + g * 8 + kc;
            uint32_t bh0 = sb_hi[off], bh1 = sb_hi[off + 4];
            uint32_t bl0 = sb_lo[off], bl1 = sb_lo[off + 4];
#pragma unroll
            for (int mi = 0; mi < 4; ++mi) {
                mma8(acc[mi][ni], Ah[mi], bh0, bh1);
                mma8(acc[mi][ni], Ah[mi], bl0, bl1);
                mma8(acc[mi][ni], Al[mi], bh0, bh1);
            }
        }
    }
}

// ---------------- small helpers ------------------------------------------------
__global__ void repack_kernel(const float* __restrict__ w) {
    int i = blockIdx.x * 256 + threadIdx.x;     // over 768*768*3, w is [co][ci][k]
    if (i >= CC * CC * 3) return;
    int k  = i % 3;
    int ci = (i / 3) % CC;
    int co = i / (3 * CC);
    g_wt[((size_t)k * CC + co) * CC + ci] = w[i];   // [k][co][ci]
}

__global__ void init_kernel() {
    int t = threadIdx.x;
    if (t < BB) g_distmax[t] = 0.0f;
    if (t < BB * 2) g_allw[t] = 1e-6f;
}

// =============== 3xTF32 mma.sync GEMM 1: residual conv =========================
// y[m,co] = x[m,co] + sum_{k,ci} x[b, n+k-1, ci] * W[co,ci,k]
// M=32768, Ntile=256 over co (768), K = 3*768 -> 144 k16 stages
__global__ __launch_bounds__(256, 1) void conv_mma_kernel(const float* __restrict__ x) {
    extern __shared__ float smf[];
    const int tid = threadIdx.x, w = tid >> 5, lane = tid & 31;
    const int co0 = blockIdx.x * 256;
    const int m0  = blockIdx.y * 128;
    const int bq  = m0 >> 11;
    const int nn0 = m0 & 2047;

    float acc[4][8][4];
#pragma unroll
    for (int a = 0; a < 4; ++a)
#pragma unroll
        for (int b = 0; b < 8; ++b)
#pragma unroll
            for (int c = 0; c < 4; ++c) acc[a][b][c] = 0.f;

    const int rA  = (w & 3) * 32 + lane;   // 0..127
    const int cA0 = (w >> 2);              // 0/1
    const int cA1 = cA0 + 2;               // 2/3

    float4 ra0, ra1, rb0, rb1, rb2, rb3;
    const float4 z4 = make_float4(0.f, 0.f, 0.f, 0.f);

#define CONV_LD(s) do { \
    int kk = (s) / 48; int ci0 = ((s) - kk * 48) * 16; \
    int r = nn0 + rA + kk - 1; \
    if (r >= 0 && r < NN) { \
        const float* pa = x + ((size_t)(bq * NN + r)) * CC + ci0; \
        ra0 = *reinterpret_cast<const float4*>(pa + cA0 * 4); \
        ra1 = *reinterpret_cast<const float4*>(pa + cA1 * 4); \
    } else { ra0 = z4; ra1 = z4; } \
    const float* pb0 = g_wt + ((size_t)(kk * CC) + co0 + rA) * CC + ci0; \
    const float* pb1 = pb0 + (size_t)128 * CC; \
    rb0 = *reinterpret_cast<const float4*>(pb0 + cA0 * 4); \
    rb1 = *reinterpret_cast<const float4*>(pb1 + cA0 * 4); \
    rb2 = *reinterpret_cast<const float4*>(pb0 + cA1 * 4); \
    rb3 = *reinterpret_cast<const float4*>(pb1 + cA1 * 4); \
} while (0)

#define GEMM_ST(buf) do { \
    split_store((buf) + A_HI, (buf) + A_LO, rA, cA0, ra0); \
    split_store((buf) + A_HI, (buf) + A_LO, rA, cA1, ra1); \
    split_store((buf) + B_HI, (buf) + B_LO, rA, cA0, rb0); \
    split_store((buf) + B_HI, (buf) + B_LO, rA + 128, cA0, rb1); \
    split_store((buf) + B_HI, (buf) + B_LO, rA, cA1, rb2); \
    split_store((buf) + B_HI, (buf) + B_LO, rA + 128, cA1, rb3); \
} while (0)

    CONV_LD(0);
    GEMM_ST(smf);
    __syncthreads();
    for (int s = 0; s < 144; ++s) {
        if (s < 143) CONV_LD(s + 1);
        mma_compute(smf + (s & 1) * BUF_F, acc, w, lane);
        if (s < 143) GEMM_ST(smf + ((s + 1) & 1) * BUF_F);
        __syncthreads();
    }

    // epilogue: residual add, 32B-sector float2 stores
    const int mbase = m0 + (w >> 2) * 64 + (lane >> 2);
    const int nbase = co0 + (w & 3) * 64 + (lane & 3) * 2;
#pragma unroll
    for (int mi = 0; mi < 4; ++mi) {
#pragma unroll
        for (int h = 0; h < 2; ++h) {
            int m = mbase + mi * 16 + h * 8;
            const float* xrow = x + (size_t)m * CC;
            float* yrow = g_y + (size_t)m * CC;
#pragma unroll
            for (int ni = 0; ni < 8; ++ni) {
                int c = nbase + ni * 8;
                float2 xv = *reinterpret_cast<const float2*>(xrow + c);
                float2 o;
                o.x = xv.x + acc[mi][ni][h * 2 + 0];
                o.y = xv.y + acc[mi][ni][h * 2 + 1];
                *reinterpret_cast<float2*>(yrow + c) = o;
            }
        }
    }
#undef CONV_LD
}

// =============== 3xTF32 mma.sync GEMM 2: Gram + dist epilogue ==================
__global__ __launch_bounds__(256, 1) void gram_mma_kernel() {
    extern __shared__ float smf[];
    const int tid = threadIdx.x, w = tid >> 5, lane = tid & 31;
    const int b  = blockIdx.z;
    const int j0 = blockIdx.x * 256;
    const int i0 = blockIdx.y * 128;
    const float* xb = g_y + (size_t)b * NN * CC;

    float acc[4][8][4];
#pragma unroll
    for (int a = 0; a < 4; ++a)
#pragma unroll
        for (int bq = 0; bq < 8; ++bq)
#pragma unroll
            for (int c = 0; c < 4; ++c) acc[a][bq][c] = 0.f;

    const int rA  = (w & 3) * 32 + lane;
    const int cA0 = (w >> 2);
    const int cA1 = cA0 + 2;

    float4 ra0, ra1, rb0, rb1, rb2, rb3;

#define GRAM_LD(s) do { \
    const float* pa = xb + (size_t)(i0 + rA) * CC + (s) * 16; \
    ra0 = *reinterpret_cast<const float4*>(pa + cA0 * 4); \
    ra1 = *reinterpret_cast<const float4*>(pa + cA1 * 4); \
    const float* pb0 = xb + (size_t)(j0 + rA) * CC + (s) * 16; \
    const float* pb1 = pb0 + (size_t)128 * CC; \
    rb0 = *reinterpret_cast<const float4*>(pb0 + cA0 * 4); \
    rb1 = *reinterpret_cast<const float4*>(pb1 + cA0 * 4); \
    rb2 = *reinterpret_cast<const float4*>(pb0 + cA1 * 4); \
    rb3 = *reinterpret_cast<const float4*>(pb1 + cA1 * 4); \
} while (0)

    GRAM_LD(0);
    GEMM_ST(smf);
    __syncthreads();
    for (int s = 0; s < 48; ++s) {
        if (s < 47) GRAM_LD(s + 1);
        mma_compute(smf + (s & 1) * BUF_F, acc, w, lane);
        if (s < 47) GEMM_ST(smf + ((s + 1) & 1) * BUF_F);
        __syncthreads();
    }

    // epilogue: dist = sqrt(max(sqi+sqj-2g,0))/sqrt(C)
    const float* sqb = g_sq + b * NN;
    const int mbase = i0 + (w >> 2) * 64 + (lane >> 2);
    const int nbase = j0 + (w & 3) * 64 + (lane & 3) * 2;
#pragma unroll
    for (int mi = 0; mi < 4; ++mi) {
#pragma unroll
        for (int h = 0; h < 2; ++h) {
            int i = mbase + mi * 16 + h * 8;
            float si = sqb[i];
            float* drow = g_dist + ((size_t)(b * NN + i)) * NN;
#pragma unroll
            for (int ni = 0; ni < 8; ++ni) {
                int j = nbase + ni * 8;
                float2 o;
                o.x = sqrtf(fmaxf(si + sqb[j]     - 2.f * acc[mi][ni][h * 2 + 0], 0.f)) * RSQRT_C;
                o.y = sqrtf(fmaxf(si + sqb[j + 1] - 2.f * acc[mi][ni][h * 2 + 1], 0.f)) * RSQRT_C;
                *reinterpret_cast<float2*>(drow + j) = o;
            }
        }
    }
#undef GRAM_LD
#undef GEMM_ST
}

// ---------------- LayerNorm + score + sq (shuffle reductions) ------------------
__global__ __launch_bounds__(256) void ln_kernel(const float* __restrict__ gamma,
                                                 const float* __restrict__ beta,
                                                 const float* __restrict__ sw,
                                                 const float* __restrict__ sbv) {
    __shared__ float red[16];
    __shared__ float bc[2];
    const int m = blockIdx.x;
    const int tid = threadIdx.x;
    const int w = tid >> 5, lane = tid & 31;
    float* yrow = g_y + (size_t)m * CC;

    float v0 = yrow[tid], v1 = yrow[tid + 256], v2 = yrow[tid + 512];
    float s = v0 + v1 + v2;
    float ss = v0 * v0 + v1 * v1 + v2 * v2;
#pragma unroll
    for (int o = 16; o; o >>= 1) {
        s  += __shfl_xor_sync(0xffffffffu, s, o);
        ss += __shfl_xor_sync(0xffffffffu, ss, o);
    }
    if (lane == 0) { red[w] = s; red[8 + w] = ss; }
    __syncthreads();
    if (tid < 32) {
        float a = (lane < 8) ? red[lane] : 0.f;
        float c = (lane < 8) ? red[8 + lane] : 0.f;
#pragma unroll
        for (int o = 4; o; o >>= 1) {
            a += __shfl_xor_sync(0xffffffffu, a, o);
            c += __shfl_xor_sync(0xffffffffu, c, o);
        }
        if (lane == 0) {
            float mu = a / (float)CC;
            float var = c / (float)CC - mu * mu;
            bc[0] = mu;
            bc[1] = 1.0f / sqrtf(var + LN_EPS);
        }
    }
    __syncthreads();
    float mu = bc[0], inv = bc[1];
    float x0 = (v0 - mu) * inv * gamma[tid]       + beta[tid];
    float x1 = (v1 - mu) * inv * gamma[tid + 256] + beta[tid + 256];
    float x2 = (v2 - mu) * inv * gamma[tid + 512] + beta[tid + 512];
    yrow[tid] = x0; yrow[tid + 256] = x1; yrow[tid + 512] = x2;

    float p = x0 * sw[tid] + x1 * sw[tid + 256] + x2 * sw[tid + 512];
    float q = x0 * x0 + x1 * x1 + x2 * x2;
#pragma unroll
    for (int o = 16; o; o >>= 1) {
        p += __shfl_xor_sync(0xffffffffu, p, o);
        q += __shfl_xor_sync(0xffffffffu, q, o);
    }
    if (lane == 0) { red[w] = p; red[8 + w] = q; }
    __syncthreads();
    if (tid == 0) {
        float pt = 0.f, qt = 0.f;
#pragma unroll
        for (int i = 0; i < 8; ++i) { pt += red[i]; qt += red[8 + i]; }
        g_sq[m] = qt;
        g_tw[m] = expf(pt + sbv[0]);
    }
}

// ---------------- top-3 smallest per row -> density; row max -> dist_max -------
__global__ __launch_bounds__(256) void knn_kernel(const float* __restrict__ noise) {
    const int m = blockIdx.x;
    const int b = m >> 11;
    const float* drow = g_dist + (size_t)m * NN;
    const int tid = threadIdx.x;

    float t0 = 1e30f, t1 = 1e30f, t2 = 1e30f, mx = 0.f;
    for (int j = tid; j < NN; j += 256) {
        float v = drow[j];
        mx = fmaxf(mx, v);
        if (v < t2) {
            if (v < t1) { t2 = t1; if (v < t0) { t1 = t0; t0 = v; } else t1 = v; }
            else t2 = v;
        }
    }
#pragma unroll
    for (int o = 16; o > 0; o >>= 1) {
        float u0 = __shfl_down_sync(0xffffffffu, t0, o);
        float u1 = __shfl_down_sync(0xffffffffu, t1, o);
        float u2 = __shfl_down_sync(0xffffffffu, t2, o);
        float um = __shfl_down_sync(0xffffffffu, mx, o);
        mx = fmaxf(mx, um);
        if (u0 < t2) { if (u0 < t1) { t2 = t1; if (u0 < t0) { t1 = t0; t0 = u0; } else t1 = u0; } else t2 = u0; }
        if (u1 < t2) { if (u1 < t1) { t2 = t1; if (u1 < t0) { t1 = t0; t0 = u1; } else t1 = u1; } else t2 = u1; }
        if (u2 < t2) { if (u2 < t1) { t2 = t1; if (u2 < t0) { t1 = t0; t0 = u2; } else t1 = u2; } else t2 = u2; }
    }
    __shared__ float s0[8], s1[8], s2[8], smx[8];
    int wid = tid >> 5, lane = tid & 31;
    if (lane == 0) { s0[wid] = t0; s1[wid] = t1; s2[wid] = t2; smx[wid] = mx; }
    __syncthreads();
    if (tid < 32) {
        t0 = (tid < 8) ? s0[tid] : 1e30f;
        t1 = (tid < 8) ? s1[tid] : 1e30f;
        t2 = (tid < 8) ? s2[tid] : 1e30f;
        mx = (tid < 8) ? smx[tid] : 0.f;
#pragma unroll
        for (int o = 4; o > 0; o >>= 1) {
            float u0 = __shfl_down_sync(0xffffffffu, t0, o);
            float u1 = __shfl_down_sync(0xffffffffu, t1, o);
            float u2 = __shfl_down_sync(0xffffffffu, t2, o);
            float um = __shfl_down_sync(0xffffffffu, mx, o);
            mx = fmaxf(mx, um);
            if (u0 < t2) { if (u0 < t1) { t2 = t1; if (u0 < t0) { t1 = t0; t0 = u0; } else t1 = u0; } else t2 = u0; }
            if (u1 < t2) { if (u1 < t1) { t2 = t1; if (u1 < t0) { t1 = t0; t0 = u1; } else t1 = u1; } else t2 = u1; }
            if (u2 < t2) { if (u2 < t1) { t2 = t1; if (u2 < t0) { t1 = t0; t0 = u2; } else t1 = u2; } else t2 = u2; }
        }
        if (tid == 0) {
            float ds = (t0 * t0 + t1 * t1 + t2 * t2) / 3.0f;
            g_density[m] = expf(-ds) + noise[m] * 1e-6f;
            atomicMax((int*)(g_distmax + b), __float_as_int(mx));   // dist >= 0
        }
    }
}

// ---------------- dist_min to higher-density point; score ----------------------
__global__ __launch_bounds__(256) void distmin_kernel() {
    __shared__ float dens[NN];
    __shared__ float red[256];
    const int m = blockIdx.x;
    const int b = m >> 11;
    const int tid = threadIdx.x;
    const float* db = g_density + b * NN;
    for (int j = tid; j < NN; j += 256) dens[j] = db[j];
    __syncthreads();

    const float di   = dens[m & 2047];
    const float dmax = g_distmax[b];
    const float* drow = g_dist + (size_t)m * NN;

    float mn = dmax;
    for (int j = tid; j < NN; j += 256) {
        float c = (dens[j] > di) ? drow[j] : dmax;
        mn = fminf(mn, c);
    }
    red[tid] = mn; __syncthreads();
    for (int o = 128; o; o >>= 1) { if (tid < o) red[tid] = fminf(red[tid], red[tid + o]); __syncthreads(); }
    if (tid == 0) g_score[m] = red[0] * di;
}

// ---------------- per-batch top-2 of score (lax.top_k tie: lower index) --------
__global__ __launch_bounds__(256) void top2_kernel() {
    __shared__ float sv[256];
    __shared__ int   si[256];
    const int b = blockIdx.x, tid = threadIdx.x;
    const float* sc = g_score + b * NN;

    float bv = -1e30f; int bi = 1 << 30;
    for (int j = tid; j < NN; j += 256) {
        float v = sc[j];
        if (v > bv || (v == bv && j < bi)) { bv = v; bi = j; }
    }
    sv[tid] = bv; si[tid] = bi; __syncthreads();
    for (int o = 128; o; o >>= 1) {
        if (tid < o) {
            float ov = sv[tid + o]; int oi = si[tid + o];
            if (ov > sv[tid] || (ov == sv[tid] && oi < si[tid])) { sv[tid] = ov; si[tid] = oi; }
        }
        __syncthreads();
    }
    int i0 = si[0];
    __syncthreads();

    bv = -1e30f; bi = 1 << 30;
    for (int j = tid; j < NN; j += 256) {
        if (j == i0) continue;
        float v = sc[j];
        if (v > bv || (v == bv && j < bi)) { bv = v; bi = j; }
    }
    sv[tid] = bv; si[tid] = bi; __syncthreads();
    for (int o = 128; o; o >>= 1) {
        if (tid < o) {
            float ov = sv[tid + o]; int oi = si[tid + o];
            if (ov > sv[tid] || (ov == sv[tid] && oi < si[tid])) { sv[tid] = ov; si[tid] = oi; }
        }
        __syncthreads();
    }
    if (tid == 0) { g_idxdown[b * 2] = i0; g_idxdown[b * 2 + 1] = si[0]; }
}

// ---------------- cluster assignment + all_weight accumulation ------------------
__global__ void assign_kernel(float* __restrict__ out) {
    int m = blockIdx.x * 256 + threadIdx.x;
    if (m >= NTOK) return;
    int b = m >> 11, n = m & 2047;
    int i0 = g_idxdown[b * 2], i1 = g_idxdown[b * 2 + 1];
    float d0 = g_dist[((size_t)(b * NN + i0)) * NN + n];
    float d1 = g_dist[((size_t)(b * NN + i1)) * NN + n];
    int cl = (d0 <= d1) ? 0 : 1;   // argmin tie -> first
    if (n == i0) cl = 0;
    if (n == i1) cl = 1;
    g_cluster[m] = cl;
    out[24576 + 32768 + m] = (float)cl;        // idx_cluster region (as float)
    atomicAdd(&g_allw[b * 2 + cl], g_tw[m]);
}

// ---------------- normalized weight output --------------------------------------
__global__ void weight_kernel(float* __restrict__ out) {
    int m = blockIdx.x * 256 + threadIdx.x;
    if (m >= NTOK) return;
    int b = m >> 11;
    float nw = g_tw[m] / g_allw[b * 2 + g_cluster[m]];
    out[24576 + m] = nw;                        // agg_weight_new region
}

// ---------------- weighted merge x_merged[b,k,:] ---------------------------------
__global__ __launch_bounds__(256) void merge_kernel(float* __restrict__ out) {
    __shared__ float wgt[NN];
    const int k = blockIdx.y, b = blockIdx.z;
    const int tid = threadIdx.x;
    const int c = blockIdx.x * 256 + tid;
    const float aw = g_allw[b * 2 + k];
    const int*   cl = g_cluster + b * NN;
    const float* tw = g_tw + b * NN;
    for (int j = tid; j < NN; j += 256)
        wgt[j] = (cl[j] == k) ? (tw[j] / aw) : 0.0f;
    __syncthreads();
    const float* xb = g_y + (size_t)b * NN * CC;
    float acc = 0.f;
    for (int n = 0; n < NN; ++n)
        acc = fmaf(xb[(size_t)n * CC + c], wgt[n], acc);
    out[(size_t)(b * 2 + k) * CC + c] = acc;    // x_merged region
}

// ---------------- launch --------------------------------------------------------
extern "C" void kernel_launch(void* const* d_in, const int* in_sizes, int n_in,
                              void* d_out, int out_size) {
    const float* x      = (const float*)d_in[0];
    const float* conv_w = (const float*)d_in[1];
    const float* gamma  = (const float*)d_in[2];
    const float* beta   = (const float*)d_in[3];
    const float* sw     = (const float*)d_in[4];
    const float* sb     = (const float*)d_in[5];
    const float* noise  = (const float*)d_in[6];
    float* out = (float*)d_out;

    cudaFuncSetAttribute(conv_mma_kernel, cudaFuncAttributeMaxDynamicSharedMemorySize, SMEM_BYTES);
    cudaFuncSetAttribute(gram_mma_kernel, cudaFuncAttributeMaxDynamicSharedMemorySize, SMEM_BYTES);

    repack_kernel<<<(CC * CC * 3 + 255) / 256, 256>>>(conv_w);
    init_kernel<<<1, 32>>>();
    conv_mma_kernel<<<dim3(CC / 256, NTOK / 128), 256, SMEM_BYTES>>>(x);
    ln_kernel<<<NTOK, 256>>>(gamma, beta, sw, sb);
    gram_mma_kernel<<<dim3(NN / 256, NN / 128, BB), 256, SMEM_BYTES>>>();
    knn_kernel<<<NTOK, 256>>>(noise);
    distmin_kernel<<<NTOK, 256>>>();
    top2_kernel<<<BB, 256>>>();
    assign_kernel<<<NTOK / 256, 256>>>(out);
    weight_kernel<<<NTOK / 256, 256>>>(out);
    merge_kernel<<<dim3(CC / 256, 2, BB), 256>>>(out);
}

// round 10
// speedup vs baseline: 1.7166x; 1.5597x over previous
#include <cuda_runtime.h>
#include <cuda_fp16.h>
#include <math.h>
#include <stdint.h>

// Problem constants
#define BB 16
#define NN 2048
#define CC 768
#define NTOK (BB*NN)          // 32768
#define LN_EPS 1e-5f
#define RSQRT_C 0.03608439182435161f   // 1/sqrt(768)
#define WSCALE 256.0f
#define INV_WSCALE 0.00390625f

// fp16 smem tile geometry: 16 k-values/row = 8 b32 words + 4 pad
#define WSTR 12
// conv kernel smem (in b32 words): A 128 rows, B 256 rows, hi+lo each
#define CA_HI 0
#define CA_LO 1536
#define CB_HI 3072
#define CB_LO 6144
#define CBUF_W 9216
#define CONV_SMEM (2*CBUF_W*4)         // 73728 B
// gram kernel smem: A,B 128 rows each + fp32 staging 128x130
#define GA_HI 0
#define GA_LO 1536
#define GB_HI 3072
#define GB_LO 4608
#define GBUF_W 6144
#define GSTG_PITCH 130
#define GRAM_SMEM (2*GBUF_W*4 + 128*GSTG_PITCH*4)   // 115712 B

// ---------------- scratch (device globals; no runtime alloc allowed) ----------
__device__ float g_y[(size_t)NTOK * CC];           // conv+LN output
__device__ float g_dist[(size_t)NTOK * NN];        // 268 MB distance matrix
__device__ float g_wt[3 * CC * CC];                // repacked conv weight [k][co][ci] * WSCALE
__device__ float g_sq[NTOK];
__device__ float g_tw[NTOK];
__device__ float g_density[NTOK];
__device__ float g_score[NTOK];
__device__ float g_distmax[BB];
__device__ int   g_idxdown[BB * 2];
__device__ float g_allw[BB * 2];
__device__ int   g_cluster[NTOK];

// ---------------- helpers -------------------------------------------------------
__device__ __forceinline__ void mma16(float* d, const uint32_t* a, uint32_t b0, uint32_t b1) {
    asm volatile(
        "mma.sync.aligned.m16n8k16.row.col.f32.f16.f16.f32 "
        "{%0,%1,%2,%3},{%4,%5,%6,%7},{%8,%9},{%0,%1,%2,%3};"
        : "+f"(d[0]), "+f"(d[1]), "+f"(d[2]), "+f"(d[3])
        : "r"(a[0]), "r"(a[1]), "r"(a[2]), "r"(a[3]), "r"(b0), "r"(b1));
}

__device__ __forceinline__ uint32_t packh2(float x, float y) {
    __half2 h = __floats2half2_rn(x, y);
    return *reinterpret_cast<uint32_t*>(&h);
}

// split float4 into fp16 hi + fp16 lo, store 8B each into smem word arrays
__device__ __forceinline__ void split_store_h(uint32_t* hi, uint32_t* lo, int row, int c4, float4 v) {
    __half h0 = __float2half_rn(v.x), h1 = __float2half_rn(v.y),
           h2 = __float2half_rn(v.z), h3 = __float2half_rn(v.w);
    float  l0 = v.x - __half2float(h0), l1 = v.y - __half2float(h1),
           l2 = v.z - __half2float(h2), l3 = v.w - __half2float(h3);
    uint32_t hp0 = ((uint32_t)__half_as_ushort(h1) << 16) | __half_as_ushort(h0);
    uint32_t hp1 = ((uint32_t)__half_as_ushort(h3) << 16) | __half_as_ushort(h2);
    *reinterpret_cast<uint2*>(hi + row * WSTR + c4 * 2) = make_uint2(hp0, hp1);
    *reinterpret_cast<uint2*>(lo + row * WSTR + c4 * 2) = make_uint2(packh2(l0, l1), packh2(l2, l3));
}

// 3xFP16 warp compute for one k16 stage. acc layout [MI*NI][4].
template<int MI, int NI>
__device__ __forceinline__ void mma_stage(const uint32_t* sah, const uint32_t* sal,
                                          const uint32_t* sbh, const uint32_t* sbl,
                                          float (*acc)[4], int mb, int nb, int kc) {
    uint32_t Ah[MI][4], Al[MI][4];
#pragma unroll
    for (int mi = 0; mi < MI; ++mi) {
        int off = (mb + mi * 16) * WSTR + kc;
        Ah[mi][0] = sah[off];            Ah[mi][1] = sah[off + 8 * WSTR];
        Ah[mi][2] = sah[off + 4];        Ah[mi][3] = sah[off + 8 * WSTR + 4];
        Al[mi][0] = sal[off];            Al[mi][1] = sal[off + 8 * WSTR];
        Al[mi][2] = sal[off + 4];        Al[mi][3] = sal[off + 8 * WSTR + 4];
    }
#pragma unroll
    for (int ni = 0; ni < NI; ++ni) {
        int off = (nb + ni * 8) * WSTR + kc;
        uint32_t bh0 = sbh[off], bh1 = sbh[off + 4];
        uint32_t bl0 = sbl[off], bl1 = sbl[off + 4];
#pragma unroll
        for (int mi = 0; mi < MI; ++mi) {
            mma16(acc[mi * NI + ni], Ah[mi], bh0, bh1);
            mma16(acc[mi * NI + ni], Ah[mi], bl0, bl1);
            mma16(acc[mi * NI + ni], Al[mi], bh0, bh1);
        }
    }
}

// ---------------- small helpers ------------------------------------------------
__global__ void repack_kernel(const float* __restrict__ w) {
    int i = blockIdx.x * 256 + threadIdx.x;     // over 768*768*3, w is [co][ci][k]
    if (i >= CC * CC * 3) return;
    int k  = i % 3;
    int ci = (i / 3) % CC;
    int co = i / (3 * CC);
    g_wt[((size_t)k * CC + co) * CC + ci] = w[i] * WSCALE;   // [k][co][ci], pre-scaled
}

__global__ void init_kernel() {
    int t = threadIdx.x;
    if (t < BB) g_distmax[t] = 0.0f;
    if (t < BB * 2) g_allw[t] = 1e-6f;
}

// =============== 3xFP16 mma GEMM 1: residual conv ==============================
// CTA 128(m) x 256(n), K = 3*768 -> 144 k16 stages. Warp tile 64x64 (2m x 4n warps).
__global__ __launch_bounds__(256, 1) void conv_mma_kernel(const float* __restrict__ x) {
    extern __shared__ uint32_t smw[];
    const int tid = threadIdx.x, w = tid >> 5, lane = tid & 31;
    const int co0 = blockIdx.x * 256;
    const int m0  = blockIdx.y * 128;
    const int bq  = m0 >> 11;
    const int nn0 = m0 & 2047;

    float acc[32][4];
#pragma unroll
    for (int a = 0; a < 32; ++a)
#pragma unroll
        for (int c = 0; c < 4; ++c) acc[a][c] = 0.f;

    const int rA  = (w & 3) * 32 + lane;   // 0..127
    const int cA0 = (w >> 2);              // 0/1
    const int cA1 = cA0 + 2;               // 2/3
    const int mb = (w >> 2) * 64 + (lane >> 2);
    const int nb = (w & 3) * 64 + (lane >> 2);
    const int kc = lane & 3;

    float4 ra0, ra1, rb0, rb1, rb2, rb3;
    const float4 z4 = make_float4(0.f, 0.f, 0.f, 0.f);

#define CONV_LD(s) do { \
    int kk = (s) / 48; int ci0 = ((s) - kk * 48) * 16; \
    int r = nn0 + rA + kk - 1; \
    if (r >= 0 && r < NN) { \
        const float* pa = x + ((size_t)(bq * NN + r)) * CC + ci0; \
        ra0 = *reinterpret_cast<const float4*>(pa + cA0 * 4); \
        ra1 = *reinterpret_cast<const float4*>(pa + cA1 * 4); \
    } else { ra0 = z4; ra1 = z4; } \
    const float* pb0 = g_wt + ((size_t)(kk * CC) + co0 + rA) * CC + ci0; \
    const float* pb1 = pb0 + (size_t)128 * CC; \
    rb0 = *reinterpret_cast<const float4*>(pb0 + cA0 * 4); \
    rb1 = *reinterpret_cast<const float4*>(pb1 + cA0 * 4); \
    rb2 = *reinterpret_cast<const float4*>(pb0 + cA1 * 4); \
    rb3 = *reinterpret_cast<const float4*>(pb1 + cA1 * 4); \
} while (0)

#define CONV_ST(bw) do { \
    uint32_t* base = smw + (bw) * CBUF_W; \
    split_store_h(base + CA_HI, base + CA_LO, rA, cA0, ra0); \
    split_store_h(base + CA_HI, base + CA_LO, rA, cA1, ra1); \
    split_store_h(base + CB_HI, base + CB_LO, rA, cA0, rb0); \
    split_store_h(base + CB_HI, base + CB_LO, rA + 128, cA0, rb1); \
    split_store_h(base + CB_HI, base + CB_LO, rA, cA1, rb2); \
    split_store_h(base + CB_HI, base + CB_LO, rA + 128, cA1, rb3); \
} while (0)

    CONV_LD(0);
    CONV_ST(0);
    __syncthreads();
    for (int s = 0; s < 144; ++s) {
        if (s < 143) CONV_LD(s + 1);
        const uint32_t* base = smw + (s & 1) * CBUF_W;
        mma_stage<4, 8>(base + CA_HI, base + CA_LO, base + CB_HI, base + CB_LO,
                        acc, mb, nb, kc);
        if (s < 143) CONV_ST((s + 1) & 1);
        __syncthreads();
    }

    // epilogue: residual add (undo weight pre-scale), float2 stores
    const int mbase = m0 + (w >> 2) * 64 + (lane >> 2);
    const int nbase = co0 + (w & 3) * 64 + (lane & 3) * 2;
#pragma unroll
    for (int mi = 0; mi < 4; ++mi) {
#pragma unroll
        for (int h = 0; h < 2; ++h) {
            int m = mbase + mi * 16 + h * 8;
            const float* xrow = x + (size_t)m * CC;
            float* yrow = g_y + (size_t)m * CC;
#pragma unroll
            for (int ni = 0; ni < 8; ++ni) {
                int c = nbase + ni * 8;
                float2 xv = *reinterpret_cast<const float2*>(xrow + c);
                float2 o;
                o.x = xv.x + acc[mi * 8 + ni][h * 2 + 0] * INV_WSCALE;
                o.y = xv.y + acc[mi * 8 + ni][h * 2 + 1] * INV_WSCALE;
                *reinterpret_cast<float2*>(yrow + c) = o;
            }
        }
    }
#undef CONV_LD
#undef CONV_ST
}

// =============== 3xFP16 mma GEMM 2: symmetric Gram + dist ======================
// 128x128 tiles, only (ib,jb) with jb>=ib; off-diagonal tiles mirror-write.
// Warp tile 32(m) x 64(n): 4 m-warps x 2 n-warps.
__global__ __launch_bounds__(256, 1) void gram_mma_kernel() {
    extern __shared__ uint32_t smw[];
    const int tid = threadIdx.x, w = tid >> 5, lane = tid & 31;
    const int b = blockIdx.z;
    // decode (ib, jb), jb >= ib, from linear index over 136 pairs
    int idx = blockIdx.x, ib = 0;
    while (idx >= 16 - ib) { idx -= 16 - ib; ++ib; }
    const int jb = ib + idx;
    const int i0 = ib * 128, j0 = jb * 128;
    const float* xb = g_y + (size_t)b * NN * CC;

    float acc[16][4];
#pragma unroll
    for (int a = 0; a < 16; ++a)
#pragma unroll
        for (int c = 0; c < 4; ++c) acc[a][c] = 0.f;

    const int half = tid >> 7, r = tid & 127;
    const size_t baserow = (size_t)((half ? j0 : i0) + r) * CC;
    const int mb = (w & 3) * 32 + (lane >> 2);
    const int nb = (w >> 2) * 64 + (lane >> 2);
    const int kc = lane & 3;

    float4 rv0, rv1, rv2, rv3;

#define GRAM_LD(s) do { \
    const float* p = xb + baserow + (s) * 16; \
    rv0 = *reinterpret_cast<const float4*>(p); \
    rv1 = *reinterpret_cast<const float4*>(p + 4); \
    rv2 = *reinterpret_cast<const float4*>(p + 8); \
    rv3 = *reinterpret_cast<const float4*>(p + 12); \
} while (0)

#define GRAM_ST(bw) do { \
    uint32_t* bh = smw + (bw) * GBUF_W + (half ? GB_HI : GA_HI); \
    uint32_t* bl = smw + (bw) * GBUF_W + (half ? GB_LO : GA_LO); \
    split_store_h(bh, bl, r, 0, rv0); \
    split_store_h(bh, bl, r, 1, rv1); \
    split_store_h(bh, bl, r, 2, rv2); \
    split_store_h(bh, bl, r, 3, rv3); \
} while (0)

    GRAM_LD(0);
    GRAM_ST(0);
    __syncthreads();
    for (int s = 0; s < 48; ++s) {
        if (s < 47) GRAM_LD(s + 1);
        const uint32_t* base = smw + (s & 1) * GBUF_W;
        mma_stage<2, 8>(base + GA_HI, base + GA_LO, base + GB_HI, base + GB_LO,
                        acc, mb, nb, kc);
        if (s < 47) GRAM_ST((s + 1) & 1);
        __syncthreads();
    }

    // epilogue: dist into padded staging, then coalesced direct + mirror stores
    float* stg = reinterpret_cast<float*>(smw + 2 * GBUF_W);
    const float* sqb = g_sq + b * NN;
    const int wm = w & 3, wn = w >> 2;
#pragma unroll
    for (int mi = 0; mi < 2; ++mi) {
#pragma unroll
        for (int c2 = 0; c2 < 2; ++c2) {
            int rr = wm * 32 + mi * 16 + (lane >> 2) + c2 * 8;
            float si = sqb[i0 + rr];
#pragma unroll
            for (int ni = 0; ni < 8; ++ni) {
#pragma unroll
                for (int c1 = 0; c1 < 2; ++c1) {
                    int cn = wn * 64 + ni * 8 + (lane & 3) * 2 + c1;
                    float g = acc[mi * 8 + ni][c2 * 2 + c1];
                    float d2 = si + sqb[j0 + cn] - 2.0f * g;
                    stg[rr * GSTG_PITCH + cn] = sqrtf(fmaxf(d2, 0.f)) * RSQRT_C;
                }
            }
        }
    }
    __syncthreads();
#pragma unroll
    for (int q = 0; q < 16; ++q) {
        int row = w * 16 + q;
        float2 v0 = *reinterpret_cast<const float2*>(stg + row * GSTG_PITCH + lane * 4);
        float2 v1 = *reinterpret_cast<const float2*>(stg + row * GSTG_PITCH + lane * 4 + 2);
        float4 o = make_float4(v0.x, v0.y, v1.x, v1.y);
        *reinterpret_cast<float4*>(g_dist + ((size_t)(b * NN + i0 + row)) * NN + j0 + lane * 4) = o;
    }
    if (ib != jb) {
#pragma unroll
        for (int q = 0; q < 16; ++q) {
            int col = w * 16 + q;
            float4 o;
            o.x = stg[(lane * 4 + 0) * GSTG_PITCH + col];
            o.y = stg[(lane * 4 + 1) * GSTG_PITCH + col];
            o.z = stg[(lane * 4 + 2) * GSTG_PITCH + col];
            o.w = stg[(lane * 4 + 3) * GSTG_PITCH + col];
            *reinterpret_cast<float4*>(g_dist + ((size_t)(b * NN + j0 + col)) * NN + i0 + lane * 4) = o;
        }
    }
#undef GRAM_LD
#undef GRAM_ST
}

// ---------------- LayerNorm + score + sq (shuffle reductions) ------------------
__global__ __launch_bounds__(256) void ln_kernel(const float* __restrict__ gamma,
                                                 const float* __restrict__ beta,
                                                 const float* __restrict__ sw,
                                                 const float* __restrict__ sbv) {
    __shared__ float red[16];
    __shared__ float bc[2];
    const int m = blockIdx.x;
    const int tid = threadIdx.x;
    const int w = tid >> 5, lane = tid & 31;
    float* yrow = g_y + (size_t)m * CC;

    float v0 = yrow[tid], v1 = yrow[tid + 256], v2 = yrow[tid + 512];
    float s = v0 + v1 + v2;
    float ss = v0 * v0 + v1 * v1 + v2 * v2;
#pragma unroll
    for (int o = 16; o; o >>= 1) {
        s  += __shfl_xor_sync(0xffffffffu, s, o);
        ss += __shfl_xor_sync(0xffffffffu, ss, o);
    }
    if (lane == 0) { red[w] = s; red[8 + w] = ss; }
    __syncthreads();
    if (tid < 32) {
        float a = (lane < 8) ? red[lane] : 0.f;
        float c = (lane < 8) ? red[8 + lane] : 0.f;
#pragma unroll
        for (int o = 4; o; o >>= 1) {
            a += __shfl_xor_sync(0xffffffffu, a, o);
            c += __shfl_xor_sync(0xffffffffu, c, o);
        }
        if (lane == 0) {
            float mu = a / (float)CC;
            float var = c / (float)CC - mu * mu;
            bc[0] = mu;
            bc[1] = 1.0f / sqrtf(var + LN_EPS);
        }
    }
    __syncthreads();
    float mu = bc[0], inv = bc[1];
    float x0 = (v0 - mu) * inv * gamma[tid]       + beta[tid];
    float x1 = (v1 - mu) * inv * gamma[tid + 256] + beta[tid + 256];
    float x2 = (v2 - mu) * inv * gamma[tid + 512] + beta[tid + 512];
    yrow[tid] = x0; yrow[tid + 256] = x1; yrow[tid + 512] = x2;

    float p = x0 * sw[tid] + x1 * sw[tid + 256] + x2 * sw[tid + 512];
    float q = x0 * x0 + x1 * x1 + x2 * x2;
#pragma unroll
    for (int o = 16; o; o >>= 1) {
        p += __shfl_xor_sync(0xffffffffu, p, o);
        q += __shfl_xor_sync(0xffffffffu, q, o);
    }
    if (lane == 0) { red[w] = p; red[8 + w] = q; }
    __syncthreads();
    if (tid == 0) {
        float pt = 0.f, qt = 0.f;
#pragma unroll
        for (int i = 0; i < 8; ++i) { pt += red[i]; qt += red[8 + i]; }
        g_sq[m] = qt;
        g_tw[m] = expf(pt + sbv[0]);
    }
}

// ---------------- top-3 smallest per row -> density; row max -> dist_max -------
__global__ __launch_bounds__(256) void knn_kernel(const float* __restrict__ noise) {
    const int m = blockIdx.x;
    const int b = m >> 11;
    const float* drow = g_dist + (size_t)m * NN;
    const int tid = threadIdx.x;

    float t0 = 1e30f, t1 = 1e30f, t2 = 1e30f, mx = 0.f;
    for (int j = tid; j < NN; j += 256) {
        float v = drow[j];
        mx = fmaxf(mx, v);
        if (v < t2) {
            if (v < t1) { t2 = t1; if (v < t0) { t1 = t0; t0 = v; } else t1 = v; }
            else t2 = v;
        }
    }
#pragma unroll
    for (int o = 16; o > 0; o >>= 1) {
        float u0 = __shfl_down_sync(0xffffffffu, t0, o);
        float u1 = __shfl_down_sync(0xffffffffu, t1, o);
        float u2 = __shfl_down_sync(0xffffffffu, t2, o);
        float um = __shfl_down_sync(0xffffffffu, mx, o);
        mx = fmaxf(mx, um);
        if (u0 < t2) { if (u0 < t1) { t2 = t1; if (u0 < t0) { t1 = t0; t0 = u0; } else t1 = u0; } else t2 = u0; }
        if (u1 < t2) { if (u1 < t1) { t2 = t1; if (u1 < t0) { t1 = t0; t0 = u1; } else t1 = u1; } else t2 = u1; }
        if (u2 < t2) { if (u2 < t1) { t2 = t1; if (u2 < t0) { t1 = t0; t0 = u2; } else t1 = u2; } else t2 = u2; }
    }
    __shared__ float s0[8], s1[8], s2[8], smx[8];
    int wid = tid >> 5, lane = tid & 31;
    if (lane == 0) { s0[wid] = t0; s1[wid] = t1; s2[wid] = t2; smx[wid] = mx; }
    __syncthreads();
    if (tid < 32) {
        t0 = (tid < 8) ? s0[tid] : 1e30f;
        t1 = (tid < 8) ? s1[tid] : 1e30f;
        t2 = (tid < 8) ? s2[tid] : 1e30f;
        mx = (tid < 8) ? smx[tid] : 0.f;
#pragma unroll
        for (int o = 4; o > 0; o >>= 1) {
            float u0 = __shfl_down_sync(0xffffffffu, t0, o);
            float u1 = __shfl_down_sync(0xffffffffu, t1, o);
            float u2 = __shfl_down_sync(0xffffffffu, t2, o);
            float um = __shfl_down_sync(0xffffffffu, mx, o);
            mx = fmaxf(mx, um);
            if (u0 < t2) { if (u0 < t1) { t2 = t1; if (u0 < t0) { t1 = t0; t0 = u0; } else t1 = u0; } else t2 = u0; }
            if (u1 < t2) { if (u1 < t1) { t2 = t1; if (u1 < t0) { t1 = t0; t0 = u1; } else t1 = u1; } else t2 = u1; }
            if (u2 < t2) { if (u2 < t1) { t2 = t1; if (u2 < t0) { t1 = t0; t0 = u2; } else t1 = u2; } else t2 = u2; }
        }
        if (tid == 0) {
            float ds = (t0 * t0 + t1 * t1 + t2 * t2) / 3.0f;
            g_density[m] = expf(-ds) + noise[m] * 1e-6f;
            atomicMax((int*)(g_distmax + b), __float_as_int(mx));   // dist >= 0
        }
    }
}

// ---------------- dist_min to higher-density point; score ----------------------
__global__ __launch_bounds__(256) void distmin_kernel() {
    __shared__ float dens[NN];
    __shared__ float red[256];
    const int m = blockIdx.x;
    const int b = m >> 11;
    const int tid = threadIdx.x;
    const float* db = g_density + b * NN;
    for (int j = tid; j < NN; j += 256) dens[j] = db[j];
    __syncthreads();

    const float di   = dens[m & 2047];
    const float dmax = g_distmax[b];
    const float* drow = g_dist + (size_t)m * NN;

    float mn = dmax;
    for (int j = tid; j < NN; j += 256) {
        float c = (dens[j] > di) ? drow[j] : dmax;
        mn = fminf(mn, c);
    }
    red[tid] = mn; __syncthreads();
    for (int o = 128; o; o >>= 1) { if (tid < o) red[tid] = fminf(red[tid], red[tid + o]); __syncthreads(); }
    if (tid == 0) g_score[m] = red[0] * di;
}

// ---------------- per-batch top-2 of score (lax.top_k tie: lower index) --------
__global__ __launch_bounds__(256) void top2_kernel() {
    __shared__ float sv[256];
    __shared__ int   si[256];
    const int b = blockIdx.x, tid = threadIdx.x;
    const float* sc = g_score + b * NN;

    float bv = -1e30f; int bi = 1 << 30;
    for (int j = tid; j < NN; j += 256) {
        float v = sc[j];
        if (v > bv || (v == bv && j < bi)) { bv = v; bi = j; }
    }
    sv[tid] = bv; si[tid] = bi; __syncthreads();
    for (int o = 128; o; o >>= 1) {
        if (tid < o) {
            float ov = sv[tid + o]; int oi = si[tid + o];
            if (ov > sv[tid] || (ov == sv[tid] && oi < si[tid])) { sv[tid] = ov; si[tid] = oi; }
        }
        __syncthreads();
    }
    int i0 = si[0];
    __syncthreads();

    bv = -1e30f; bi = 1 << 30;
    for (int j = tid; j < NN; j += 256) {
        if (j == i0) continue;
        float v = sc[j];
        if (v > bv || (v == bv && j < bi)) { bv = v; bi = j; }
    }
    sv[tid] = bv; si[tid] = bi; __syncthreads();
    for (int o = 128; o; o >>= 1) {
        if (tid < o) {
            float ov = sv[tid + o]; int oi = si[tid + o];
            if (ov > sv[tid] || (ov == sv[tid] && oi < si[tid])) { sv[tid] = ov; si[tid] = oi; }
        }
        __syncthreads();
    }
    if (tid == 0) { g_idxdown[b * 2] = i0; g_idxdown[b * 2 + 1] = si[0]; }
}

// ---------------- cluster assignment + all_weight accumulation ------------------
__global__ void assign_kernel(float* __restrict__ out) {
    int m = blockIdx.x * 256 + threadIdx.x;
    if (m >= NTOK) return;
    int b = m >> 11, n = m & 2047;
    int i0 = g_idxdown[b * 2], i1 = g_idxdown[b * 2 + 1];
    float d0 = g_dist[((size_t)(b * NN + i0)) * NN + n];
    float d1 = g_dist[((size_t)(b * NN + i1)) * NN + n];
    int cl = (d0 <= d1) ? 0 : 1;   // argmin tie -> first
    if (n == i0) cl = 0;
    if (n == i1) cl = 1;
    g_cluster[m] = cl;
    out[24576 + 32768 + m] = (float)cl;        // idx_cluster region (as float)
    atomicAdd(&g_allw[b * 2 + cl], g_tw[m]);
}

// ---------------- normalized weight output --------------------------------------
__global__ void weight_kernel(float* __restrict__ out) {
    int m = blockIdx.x * 256 + threadIdx.x;
    if (m >= NTOK) return;
    int b = m >> 11;
    float nw = g_tw[m] / g_allw[b * 2 + g_cluster[m]];
    out[24576 + m] = nw;                        // agg_weight_new region
}

// ---------------- weighted merge x_merged[b,k,:] ---------------------------------
__global__ __launch_bounds__(256) void merge_kernel(float* __restrict__ out) {
    __shared__ float wgt[NN];
    const int k = blockIdx.y, b = blockIdx.z;
    const int tid = threadIdx.x;
    const int c = blockIdx.x * 256 + tid;
    const float aw = g_allw[b * 2 + k];
    const int*   cl = g_cluster + b * NN;
    const float* tw = g_tw + b * NN;
    for (int j = tid; j < NN; j += 256)
        wgt[j] = (cl[j] == k) ? (tw[j] / aw) : 0.0f;
    __syncthreads();
    const float* xb = g_y + (size_t)b * NN * CC;
    float acc = 0.f;
    for (int n = 0; n < NN; ++n)
        acc = fmaf(xb[(size_t)n * CC + c], wgt[n], acc);
    out[(size_t)(b * 2 + k) * CC + c] = acc;    // x_merged region
}

// ---------------- launch --------------------------------------------------------
extern "C" void kernel_launch(void* const* d_in, const int* in_sizes, int n_in,
                              void* d_out, int out_size) {
    const float* x      = (const float*)d_in[0];
    const float* conv_w = (const float*)d_in[1];
    const float* gamma  = (const float*)d_in[2];
    const float* beta   = (const float*)d_in[3];
    const float* sw     = (const float*)d_in[4];
    const float* sb     = (const float*)d_in[5];
    const float* noise  = (const float*)d_in[6];
    float* out = (float*)d_out;

    cudaFuncSetAttribute(conv_mma_kernel, cudaFuncAttributeMaxDynamicSharedMemorySize, CONV_SMEM);
    cudaFuncSetAttribute(gram_mma_kernel, cudaFuncAttributeMaxDynamicSharedMemorySize, GRAM_SMEM);

    repack_kernel<<<(CC * CC * 3 + 255) / 256, 256>>>(conv_w);
    init_kernel<<<1, 32>>>();
    conv_mma_kernel<<<dim3(CC / 256, NTOK / 128), 256, CONV_SMEM>>>(x);
    ln_kernel<<<NTOK, 256>>>(gamma, beta, sw, sb);
    gram_mma_kernel<<<dim3(136, 1, BB), 256, GRAM_SMEM>>>();
    knn_kernel<<<NTOK, 256>>>(noise);
    distmin_kernel<<<NTOK, 256>>>();
    top2_kernel<<<BB, 256>>>();
    assign_kernel<<<NTOK / 256, 256>>>(out);
    weight_kernel<<<NTOK / 256, 256>>>(out);
    merge_kernel<<<dim3(CC / 256, 2, BB), 256>>>(out);
}

// round 13
// speedup vs baseline: 1.9607x; 1.1422x over previous
#include <cuda_runtime.h>
#include <cuda_fp16.h>
#include <math.h>
#include <stdint.h>

// Problem constants
#define BB 16
#define NN 2048
#define CC 768
#define NTOK (BB*NN)          // 32768
#define LN_EPS 1e-5f
#define RSQRT_C 0.03608439182435161f   // 1/sqrt(768)
#define WSCALE 256.0f
#define INV_WSCALE 0.00390625f

// fp16 smem tile geometry: one k16 chunk/row = 8 b32 words + 4 pad = 48B
#define WSTR 12
// conv stage buffer (words): A 128 rows hi+lo (3072), B 256 rows hi+lo (6144)
#define CA_LO (128*WSTR)          // 1536
#define CB_HI (128*WSTR*2)        // 3072
#define CB_LO (CB_HI + 256*WSTR)  // 6144
#define CBUF_W (128*WSTR*2 + 256*WSTR*2)      // 9216
#define CONV_SMEM (4*CBUF_W*4)                 // 147456 B, 4-stage pipeline
// gram stage buffer: A 128 + B 128 rows, hi+lo
#define GA_LO (128*WSTR)
#define GB_HI (256*WSTR)
#define GB_LO (256*WSTR + 128*WSTR)
#define GBUF_W (128*WSTR*2 + 128*WSTR*2)      // 6144
#define GSTG_PITCH 130
#define GRAM_SMEM (4*GBUF_W*4)                 // 98304 B (reused as fp32 staging)

// ---------------- scratch (device globals; no runtime alloc allowed) ----------
__device__ float  g_y[(size_t)NTOK * CC];          // conv+LN output (fp32, for merge)
__device__ float  g_dist[(size_t)NTOK * NN];       // 268 MB distance matrix
__device__ __half g_xh[(size_t)NTOK * CC];         // x split hi
__device__ __half g_xl[(size_t)NTOK * CC];         // x split lo
__device__ __half g_yh[(size_t)NTOK * CC];         // LN(y) split hi
__device__ __half g_yl[(size_t)NTOK * CC];         // LN(y) split lo
__device__ __half g_wh[3 * CC * CC];               // W*256 split hi  [k][co][ci]
__device__ __half g_wl[3 * CC * CC];               // W*256 split lo
__device__ float  g_sq[NTOK];
__device__ float  g_tw[NTOK];
__device__ float  g_density[NTOK];
__device__ float  g_score[NTOK];
__device__ float  g_distmax[BB];
__device__ int    g_idxdown[BB * 2];
__device__ float  g_allw[BB * 2];
__device__ int    g_cluster[NTOK];

// ---------------- helpers -------------------------------------------------------
__device__ __forceinline__ uint32_t smem_u32(const void* p) {
    uint32_t a;
    asm("{ .reg .u64 t; cvta.to.shared.u64 t, %1; cvt.u32.u64 %0, t; }" : "=r"(a) : "l"(p));
    return a;
}

__device__ __forceinline__ void mma16(float* d, const uint32_t* a, uint32_t b0, uint32_t b1) {
    asm volatile(
        "mma.sync.aligned.m16n8k16.row.col.f32.f16.f16.f32 "
        "{%0,%1,%2,%3},{%4,%5,%6,%7},{%8,%9},{%0,%1,%2,%3};"
        : "+f"(d[0]), "+f"(d[1]), "+f"(d[2]), "+f"(d[3])
        : "r"(a[0]), "r"(a[1]), "r"(a[2]), "r"(a[3]), "r"(b0), "r"(b1));
}

#define CP_ASYNC16(dst, src, sz) \
    asm volatile("cp.async.cg.shared.global [%0], [%1], 16, %2;" \
                 :: "r"(dst), "l"(src), "r"(sz) : "memory")
#define CP_COMMIT() asm volatile("cp.async.commit_group;" ::: "memory")
#define CP_WAIT3()  asm volatile("cp.async.wait_group 3;" ::: "memory")
#define CP_WAIT0()  asm volatile("cp.async.wait_group 0;" ::: "memory")

// 3xFP16 warp compute for one k16 stage. acc layout [MI*NI][4].
template<int MI, int NI>
__device__ __forceinline__ void mma_stage(const uint32_t* sah, const uint32_t* sal,
                                          const uint32_t* sbh, const uint32_t* sbl,
                                          float (*acc)[4], int mb, int nb, int kc) {
    uint32_t Ah[MI][4], Al[MI][4];
#pragma unroll
    for (int mi = 0; mi < MI; ++mi) {
        int off = (mb + mi * 16) * WSTR + kc;
        Ah[mi][0] = sah[off];            Ah[mi][1] = sah[off + 8 * WSTR];
        Ah[mi][2] = sah[off + 4];        Ah[mi][3] = sah[off + 8 * WSTR + 4];
        Al[mi][0] = sal[off];            Al[mi][1] = sal[off + 8 * WSTR];
        Al[mi][2] = sal[off + 4];        Al[mi][3] = sal[off + 8 * WSTR + 4];
    }
#pragma unroll
    for (int ni = 0; ni < NI; ++ni) {
        int off = (nb + ni * 8) * WSTR + kc;
        uint32_t bh0 = sbh[off], bh1 = sbh[off + 4];
        uint32_t bl0 = sbl[off], bl1 = sbl[off + 4];
#pragma unroll
        for (int mi = 0; mi < MI; ++mi) {
            mma16(acc[mi * NI + ni], Ah[mi], bh0, bh1);
            mma16(acc[mi * NI + ni], Ah[mi], bl0, bl1);
            mma16(acc[mi * NI + ni], Al[mi], bh0, bh1);
        }
    }
}

// ---------------- prep kernels ---------------------------------------------------
__global__ void prep_x_kernel(const float* __restrict__ x) {
    size_t i = ((size_t)blockIdx.x * 256 + threadIdx.x) * 8;
    float4 a = *reinterpret_cast<const float4*>(x + i);
    float4 b = *reinterpret_cast<const float4*>(x + i + 4);
    __half h[8]; float v[8] = {a.x, a.y, a.z, a.w, b.x, b.y, b.z, b.w};
#pragma unroll
    for (int t = 0; t < 8; ++t) h[t] = __float2half_rn(v[t]);
    *reinterpret_cast<uint4*>(g_xh + i) = *reinterpret_cast<uint4*>(h);
#pragma unroll
    for (int t = 0; t < 8; ++t) h[t] = __float2half_rn(v[t] - __half2float(h[t]));
    *reinterpret_cast<uint4*>(g_xl + i) = *reinterpret_cast<uint4*>(h);
}

__global__ void repack_kernel(const float* __restrict__ w) {
    int i = blockIdx.x * 256 + threadIdx.x;     // over 768*768*3, w is [co][ci][k]
    if (i >= CC * CC * 3) return;
    int k  = i % 3;
    int ci = (i / 3) % CC;
    int co = i / (3 * CC);
    float v = w[i] * WSCALE;
    __half hi = __float2half_rn(v);
    size_t o = ((size_t)k * CC + co) * CC + ci;
    g_wh[o] = hi;
    g_wl[o] = __float2half_rn(v - __half2float(hi));
}

__global__ void init_kernel() {
    int t = threadIdx.x;
    if (t < BB) g_distmax[t] = 0.0f;
    if (t < BB * 2) g_allw[t] = 1e-6f;
}

// =============== 3xFP16 mma GEMM 1: residual conv ==============================
// CTA 128(m) x 256(n), K = 3*768 -> 144 k16 stages, 4-deep cp.async pipeline.
__global__ __launch_bounds__(256, 1) void conv_mma_kernel(const float* __restrict__ x) {
    extern __shared__ uint32_t smw[];
    const int tid = threadIdx.x, w = tid >> 5, lane = tid & 31;
    const int co0 = blockIdx.x * 256;
    const int m0  = blockIdx.y * 128;
    const int bq  = m0 >> 11;
    const int nn0 = m0 & 2047;
    const uint32_t smbase = smem_u32(smw);

    // per-thread cp.async chunk descriptors (6 chunks of 16B per stage)
    int crow[6], cpart[6], chalf[6], cisB[6]; uint32_t cdst[6];
#pragma unroll
    for (int t = 0; t < 6; ++t) {
        int c = t * 256 + tid;
        int isB = c >= 512;
        int d = isB ? c - 512 : c;
        int row = d >> 2, part = (d >> 1) & 1, hf = d & 1;
        crow[t] = row; cpart[t] = part; chalf[t] = hf; cisB[t] = isB;
        cdst[t] = (uint32_t)((isB ? (CB_HI + part * 256 * WSTR)
                                  : (part * 128 * WSTR)) + row * WSTR + hf * 4) * 4;
    }

#define CONV_ISSUE(s) do { \
    int kk = (s) / 48, ci = (s) - kk * 48; \
    uint32_t sb = smbase + (((s) & 3) * CBUF_W) * 4; \
    _Pragma("unroll") \
    for (int t = 0; t < 6; ++t) { \
        const __half* src; int sz = 16; \
        if (!cisB[t]) { \
            int r = nn0 + crow[t] + kk - 1; \
            if (r < 0 || r >= NN) { sz = 0; r = 0; } \
            src = (cpart[t] ? g_xl : g_xh) + ((size_t)(bq * NN + r) * CC + ci * 16 + chalf[t] * 8); \
        } else { \
            src = (cpart[t] ? g_wl : g_wh) + (((size_t)kk * CC + co0 + crow[t]) * CC + ci * 16 + chalf[t] * 8); \
        } \
        CP_ASYNC16(sb + cdst[t], src, sz); \
    } \
    CP_COMMIT(); \
} while (0)

    float acc[32][4];
#pragma unroll
    for (int a = 0; a < 32; ++a)
#pragma unroll
        for (int c = 0; c < 4; ++c) acc[a][c] = 0.f;

    const int mb = (w >> 2) * 64 + (lane >> 2);
    const int nb = (w & 3) * 64 + (lane >> 2);
    const int kc = lane & 3;

    CONV_ISSUE(0); CONV_ISSUE(1); CONV_ISSUE(2);
    for (int s = 0; s < 144; ++s) {
        if (s + 3 < 144) { CONV_ISSUE(s + 3); } else { CP_COMMIT(); }
        CP_WAIT3();
        __syncthreads();
        const uint32_t* base = smw + (s & 3) * CBUF_W;
        mma_stage<4, 8>(base, base + CA_LO, base + CB_HI, base + CB_LO,
                        acc, mb, nb, kc);
        __syncthreads();
    }
#undef CONV_ISSUE

    // epilogue: residual add (undo weight pre-scale), float2 stores
    const int mbase = m0 + (w >> 2) * 64 + (lane >> 2);
    const int nbase = co0 + (w & 3) * 64 + (lane & 3) * 2;
#pragma unroll
    for (int mi = 0; mi < 4; ++mi) {
#pragma unroll
        for (int h = 0; h < 2; ++h) {
            int m = mbase + mi * 16 + h * 8;
            const float* xrow = x + (size_t)m * CC;
            float* yrow = g_y + (size_t)m * CC;
#pragma unroll
            for (int ni = 0; ni < 8; ++ni) {
                int c = nbase + ni * 8;
                float2 xv = *reinterpret_cast<const float2*>(xrow + c);
                float2 o;
                o.x = xv.x + acc[mi * 8 + ni][h * 2 + 0] * INV_WSCALE;
                o.y = xv.y + acc[mi * 8 + ni][h * 2 + 1] * INV_WSCALE;
                *reinterpret_cast<float2*>(yrow + c) = o;
            }
        }
    }
}

// =============== 3xFP16 mma GEMM 2: symmetric Gram + dist ======================
// 128x128 tiles, only jb>=ib; mirror-write off-diagonal. 4-deep cp.async pipeline.
__global__ __launch_bounds__(256, 1) void gram_mma_kernel() {
    extern __shared__ uint32_t smw[];
    const int tid = threadIdx.x, w = tid >> 5, lane = tid & 31;
    const int b = blockIdx.z;
    int idx = blockIdx.x, ib = 0;
    while (idx >= 16 - ib) { idx -= 16 - ib; ++ib; }
    const int jb = ib + idx;
    const int i0 = ib * 128, j0 = jb * 128;
    const uint32_t smbase = smem_u32(smw);

    // per-thread chunk descriptors (4 chunks per stage)
    int crow[4], cpart[4], chalf[4], cisB[4]; uint32_t cdst[4];
#pragma unroll
    for (int t = 0; t < 4; ++t) {
        int c = t * 256 + tid;
        int isB = c >= 512;
        int d = isB ? c - 512 : c;
        int row = d >> 2, part = (d >> 1) & 1, hf = d & 1;
        crow[t] = row; cpart[t] = part; chalf[t] = hf; cisB[t] = isB;
        cdst[t] = (uint32_t)((isB ? GB_HI : 0) + part * 128 * WSTR + row * WSTR + hf * 4) * 4;
    }

#define GRAM_ISSUE(s) do { \
    uint32_t sb = smbase + (((s) & 3) * GBUF_W) * 4; \
    _Pragma("unroll") \
    for (int t = 0; t < 4; ++t) { \
        int base0 = cisB[t] ? j0 : i0; \
        const __half* src = (cpart[t] ? g_yl : g_yh) + \
            ((size_t)(b * NN + base0 + crow[t]) * CC + (s) * 16 + chalf[t] * 8); \
        CP_ASYNC16(sb + cdst[t], src, 16); \
    } \
    CP_COMMIT(); \
} while (0)

    float acc[16][4];
#pragma unroll
    for (int a = 0; a < 16; ++a)
#pragma unroll
        for (int c = 0; c < 4; ++c) acc[a][c] = 0.f;

    const int mb = (w & 3) * 32 + (lane >> 2);
    const int nb = (w >> 2) * 64 + (lane >> 2);
    const int kc = lane & 3;

    GRAM_ISSUE(0); GRAM_ISSUE(1); GRAM_ISSUE(2);
    for (int s = 0; s < 48; ++s) {
        if (s + 3 < 48) { GRAM_ISSUE(s + 3); } else { CP_COMMIT(); }
        CP_WAIT3();
        __syncthreads();
        const uint32_t* base = smw + (s & 3) * GBUF_W;
        mma_stage<2, 8>(base, base + GA_LO, base + GB_HI, base + GB_LO,
                        acc, mb, nb, kc);
        __syncthreads();
    }
#undef GRAM_ISSUE
    CP_WAIT0();
    __syncthreads();

    // epilogue: dist into padded staging (reuse pipeline smem), then coalesced stores
    float* stg = reinterpret_cast<float*>(smw);
    const float* sqb = g_sq + b * NN;
    const int wm = w & 3, wn = w >> 2;
#pragma unroll
    for (int mi = 0; mi < 2; ++mi) {
#pragma unroll
        for (int c2 = 0; c2 < 2; ++c2) {
            int rr = wm * 32 + mi * 16 + (lane >> 2) + c2 * 8;
            float si = sqb[i0 + rr];
#pragma unroll
            for (int ni = 0; ni < 8; ++ni) {
#pragma unroll
                for (int c1 = 0; c1 < 2; ++c1) {
                    int cn = wn * 64 + ni * 8 + (lane & 3) * 2 + c1;
                    float g = acc[mi * 8 + ni][c2 * 2 + c1];
                    float d2 = si + sqb[j0 + cn] - 2.0f * g;
                    stg[rr * GSTG_PITCH + cn] = sqrtf(fmaxf(d2, 0.f)) * RSQRT_C;
                }
            }
        }
    }
    __syncthreads();
#pragma unroll
    for (int q = 0; q < 16; ++q) {
        int row = w * 16 + q;
        float2 v0 = *reinterpret_cast<const float2*>(stg + row * GSTG_PITCH + lane * 4);
        float2 v1 = *reinterpret_cast<const float2*>(stg + row * GSTG_PITCH + lane * 4 + 2);
        float4 o = make_float4(v0.x, v0.y, v1.x, v1.y);
        *reinterpret_cast<float4*>(g_dist + ((size_t)(b * NN + i0 + row)) * NN + j0 + lane * 4) = o;
    }
    if (ib != jb) {
#pragma unroll
        for (int q = 0; q < 16; ++q) {
            int col = w * 16 + q;
            float4 o;
            o.x = stg[(lane * 4 + 0) * GSTG_PITCH + col];
            o.y = stg[(lane * 4 + 1) * GSTG_PITCH + col];
            o.z = stg[(lane * 4 + 2) * GSTG_PITCH + col];
            o.w = stg[(lane * 4 + 3) * GSTG_PITCH + col];
            *reinterpret_cast<float4*>(g_dist + ((size_t)(b * NN + j0 + col)) * NN + i0 + lane * 4) = o;
        }
    }
}

// ---------------- LayerNorm + score + sq + fp16 split (shuffle reductions) -----
__global__ __launch_bounds__(256) void ln_kernel(const float* __restrict__ gamma,
                                                 const float* __restrict__ beta,
                                                 const float* __restrict__ sw,
                                                 const float* __restrict__ sbv) {
    __shared__ float red[16];
    __shared__ float bc[2];
    const int m = blockIdx.x;
    const int tid = threadIdx.x;
    const int w = tid >> 5, lane = tid & 31;
    float* yrow = g_y + (size_t)m * CC;

    float v0 = yrow[tid], v1 = yrow[tid + 256], v2 = yrow[tid + 512];
    float s = v0 + v1 + v2;
    float ss = v0 * v0 + v1 * v1 + v2 * v2;
#pragma unroll
    for (int o = 16; o; o >>= 1) {
        s  += __shfl_xor_sync(0xffffffffu, s, o);
        ss += __shfl_xor_sync(0xffffffffu, ss, o);
    }
    if (lane == 0) { red[w] = s; red[8 + w] = ss; }
    __syncthreads();
    if (tid < 32) {
        float a = (lane < 8) ? red[lane] : 0.f;
        float c = (lane < 8) ? red[8 + lane] : 0.f;
#pragma unroll
        for (int o = 4; o; o >>= 1) {
            a += __shfl_xor_sync(0xffffffffu, a, o);
            c += __shfl_xor_sync(0xffffffffu, c, o);
        }
        if (lane == 0) {
            float mu = a / (float)CC;
            float var = c / (float)CC - mu * mu;
            bc[0] = mu;
            bc[1] = 1.0f / sqrtf(var + LN_EPS);
        }
    }
    __syncthreads();
    float mu = bc[0], inv = bc[1];
    float x0 = (v0 - mu) * inv * gamma[tid]       + beta[tid];
    float x1 = (v1 - mu) * inv * gamma[tid + 256] + beta[tid + 256];
    float x2 = (v2 - mu) * inv * gamma[tid + 512] + beta[tid + 512];
    yrow[tid] = x0; yrow[tid + 256] = x1; yrow[tid + 512] = x2;

    // fp16 hi/lo split for gram GEMM
    __half* yh = g_yh + (size_t)m * CC;
    __half* yl = g_yl + (size_t)m * CC;
    __half h0 = __float2half_rn(x0), h1 = __float2half_rn(x1), h2 = __float2half_rn(x2);
    yh[tid] = h0; yh[tid + 256] = h1; yh[tid + 512] = h2;
    yl[tid]       = __float2half_rn(x0 - __half2float(h0));
    yl[tid + 256] = __float2half_rn(x1 - __half2float(h1));
    yl[tid + 512] = __float2half_rn(x2 - __half2float(h2));

    float p = x0 * sw[tid] + x1 * sw[tid + 256] + x2 * sw[tid + 512];
    float q = x0 * x0 + x1 * x1 + x2 * x2;
#pragma unroll
    for (int o = 16; o; o >>= 1) {
        p += __shfl_xor_sync(0xffffffffu, p, o);
        q += __shfl_xor_sync(0xffffffffu, q, o);
    }
    if (lane == 0) { red[w] = p; red[8 + w] = q; }
    __syncthreads();
    if (tid == 0) {
        float pt = 0.f, qt = 0.f;
#pragma unroll
        for (int i = 0; i < 8; ++i) { pt += red[i]; qt += red[8 + i]; }
        g_sq[m] = qt;
        g_tw[m] = expf(pt + sbv[0]);
    }
}

// ---------------- top-3 smallest per row -> density; row max -> dist_max -------
__global__ __launch_bounds__(256) void knn_kernel(const float* __restrict__ noise) {
    const int m = blockIdx.x;
    const int b = m >> 11;
    const float* drow = g_dist + (size_t)m * NN;
    const int tid = threadIdx.x;

    float t0 = 1e30f, t1 = 1e30f, t2 = 1e30f, mx = 0.f;
    for (int j = tid; j < NN; j += 256) {
        float v = drow[j];
        mx = fmaxf(mx, v);
        if (v < t2) {
            if (v < t1) { t2 = t1; if (v < t0) { t1 = t0; t0 = v; } else t1 = v; }
            else t2 = v;
        }
    }
#pragma unroll
    for (int o = 16; o > 0; o >>= 1) {
        float u0 = __shfl_down_sync(0xffffffffu, t0, o);
        float u1 = __shfl_down_sync(0xffffffffu, t1, o);
        float u2 = __shfl_down_sync(0xffffffffu, t2, o);
        float um = __shfl_down_sync(0xffffffffu, mx, o);
        mx = fmaxf(mx, um);
        if (u0 < t2) { if (u0 < t1) { t2 = t1; if (u0 < t0) { t1 = t0; t0 = u0; } else t1 = u0; } else t2 = u0; }
        if (u1 < t2) { if (u1 < t1) { t2 = t1; if (u1 < t0) { t1 = t0; t0 = u1; } else t1 = u1; } else t2 = u1; }
        if (u2 < t2) { if (u2 < t1) { t2 = t1; if (u2 < t0) { t1 = t0; t0 = u2; } else t1 = u2; } else t2 = u2; }
    }
    __shared__ float s0[8], s1[8], s2[8], smx[8];
    int wid = tid >> 5, lane = tid & 31;
    if (lane == 0) { s0[wid] = t0; s1[wid] = t1; s2[wid] = t2; smx[wid] = mx; }
    __syncthreads();
    if (tid < 32) {
        t0 = (tid < 8) ? s0[tid] : 1e30f;
        t1 = (tid < 8) ? s1[tid] : 1e30f;
        t2 = (tid < 8) ? s2[tid] : 1e30f;
        mx = (tid < 8) ? smx[tid] : 0.f;
#pragma unroll
        for (int o = 4; o > 0; o >>= 1) {
            float u0 = __shfl_down_sync(0xffffffffu, t0, o);
            float u1 = __shfl_down_sync(0xffffffffu, t1, o);
            float u2 = __shfl_down_sync(0xffffffffu, t2, o);
            float um = __shfl_down_sync(0xffffffffu, mx, o);
            mx = fmaxf(mx, um);
            if (u0 < t2) { if (u0 < t1) { t2 = t1; if (u0 < t0) { t1 = t0; t0 = u0; } else t1 = u0; } else t2 = u0; }
            if (u1 < t2) { if (u1 < t1) { t2 = t1; if (u1 < t0) { t1 = t0; t0 = u1; } else t1 = u1; } else t2 = u1; }
            if (u2 < t2) { if (u2 < t1) { t2 = t1; if (u2 < t0) { t1 = t0; t0 = u2; } else t1 = u2; } else t2 = u2; }
        }
        if (tid == 0) {
            float ds = (t0 * t0 + t1 * t1 + t2 * t2) / 3.0f;
            g_density[m] = expf(-ds) + noise[m] * 1e-6f;
            atomicMax((int*)(g_distmax + b), __float_as_int(mx));   // dist >= 0
        }
    }
}

// ---------------- dist_min to higher-density point; score ----------------------
__global__ __launch_bounds__(256) void distmin_kernel() {
    __shared__ float dens[NN];
    __shared__ float red[256];
    const int m = blockIdx.x;
    const int b = m >> 11;
    const int tid = threadIdx.x;
    const float* db = g_density + b * NN;
    for (int j = tid; j < NN; j += 256) dens[j] = db[j];
    __syncthreads();

    const float di   = dens[m & 2047];
    const float dmax = g_distmax[b];
    const float* drow = g_dist + (size_t)m * NN;

    float mn = dmax;
    for (int j = tid; j < NN; j += 256) {
        float c = (dens[j] > di) ? drow[j] : dmax;
        mn = fminf(mn, c);
    }
    red[tid] = mn; __syncthreads();
    for (int o = 128; o; o >>= 1) { if (tid < o) red[tid] = fminf(red[tid], red[tid + o]); __syncthreads(); }
    if (tid == 0) g_score[m] = red[0] * di;
}

// ---------------- per-batch top-2 of score (lax.top_k tie: lower index) --------
__global__ __launch_bounds__(256) void top2_kernel() {
    __shared__ float sv[256];
    __shared__ int   si[256];
    const int b = blockIdx.x, tid = threadIdx.x;
    const float* sc = g_score + b * NN;

    float bv = -1e30f; int bi = 1 << 30;
    for (int j = tid; j < NN; j += 256) {
        float v = sc[j];
        if (v > bv || (v == bv && j < bi)) { bv = v; bi = j; }
    }
    sv[tid] = bv; si[tid] = bi; __syncthreads();
    for (int o = 128; o; o >>= 1) {
        if (tid < o) {
            float ov = sv[tid + o]; int oi = si[tid + o];
            if (ov > sv[tid] || (ov == sv[tid] && oi < si[tid])) { sv[tid] = ov; si[tid] = oi; }
        }
        __syncthreads();
    }
    int i0 = si[0];
    __syncthreads();

    bv = -1e30f; bi = 1 << 30;
    for (int j = tid; j < NN; j += 256) {
        if (j == i0) continue;
        float v = sc[j];
        if (v > bv || (v == bv && j < bi)) { bv = v; bi = j; }
    }
    sv[tid] = bv; si[tid] = bi; __syncthreads();
    for (int o = 128; o; o >>= 1) {
        if (tid < o) {
            float ov = sv[tid + o]; int oi = si[tid + o];
            if (ov > sv[tid] || (ov == sv[tid] && oi < si[tid])) { sv[tid] = ov; si[tid] = oi; }
        }
        __syncthreads();
    }
    if (tid == 0) { g_idxdown[b * 2] = i0; g_idxdown[b * 2 + 1] = si[0]; }
}

// ---------------- cluster assignment + all_weight accumulation ------------------
__global__ void assign_kernel(float* __restrict__ out) {
    int m = blockIdx.x * 256 + threadIdx.x;
    if (m >= NTOK) return;
    int b = m >> 11, n = m & 2047;
    int i0 = g_idxdown[b * 2], i1 = g_idxdown[b * 2 + 1];
    float d0 = g_dist[((size_t)(b * NN + i0)) * NN + n];
    float d1 = g_dist[((size_t)(b * NN + i1)) * NN + n];
    int cl = (d0 <= d1) ? 0 : 1;   // argmin tie -> first
    if (n == i0) cl = 0;
    if (n == i1) cl = 1;
    g_cluster[m] = cl;
    out[24576 + 32768 + m] = (float)cl;        // idx_cluster region (as float)
    atomicAdd(&g_allw[b * 2 + cl], g_tw[m]);
}

// ---------------- normalized weight output --------------------------------------
__global__ void weight_kernel(float* __restrict__ out) {
    int m = blockIdx.x * 256 + threadIdx.x;
    if (m >= NTOK) return;
    int b = m >> 11;
    float nw = g_tw[m] / g_allw[b * 2 + g_cluster[m]];
    out[24576 + m] = nw;                        // agg_weight_new region
}

// ---------------- weighted merge x_merged[b,k,:] ---------------------------------
__global__ __launch_bounds__(256) void merge_kernel(float* __restrict__ out) {
    __shared__ float wgt[NN];
    const int k = blockIdx.y, b = blockIdx.z;
    const int tid = threadIdx.x;
    const int c = blockIdx.x * 256 + tid;
    const float aw = g_allw[b * 2 + k];
    const int*   cl = g_cluster + b * NN;
    const float* tw = g_tw + b * NN;
    for (int j = tid; j < NN; j += 256)
        wgt[j] = (cl[j] == k) ? (tw[j] / aw) : 0.0f;
    __syncthreads();
    const float* xb = g_y + (size_t)b * NN * CC;
    float acc = 0.f;
    for (int n = 0; n < NN; ++n)
        acc = fmaf(xb[(size_t)n * CC + c], wgt[n], acc);
    out[(size_t)(b * 2 + k) * CC + c] = acc;    // x_merged region
}

// ---------------- launch --------------------------------------------------------
extern "C" void kernel_launch(void* const* d_in, const int* in_sizes, int n_in,
                              void* d_out, int out_size) {
    const float* x      = (const float*)d_in[0];
    const float* conv_w = (const float*)d_in[1];
    const float* gamma  = (const float*)d_in[2];
    const float* beta   = (const float*)d_in[3];
    const float* sw     = (const float*)d_in[4];
    const float* sb     = (const float*)d_in[5];
    const float* noise  = (const float*)d_in[6];
    float* out = (float*)d_out;

    cudaFuncSetAttribute(conv_mma_kernel, cudaFuncAttributeMaxDynamicSharedMemorySize, CONV_SMEM);
    cudaFuncSetAttribute(gram_mma_kernel, cudaFuncAttributeMaxDynamicSharedMemorySize, GRAM_SMEM);

    repack_kernel<<<(CC * CC * 3 + 255) / 256, 256>>>(conv_w);
    prep_x_kernel<<<(NTOK * CC / 8) / 256, 256>>>(x);
    init_kernel<<<1, 32>>>();
    conv_mma_kernel<<<dim3(CC / 256, NTOK / 128), 256, CONV_SMEM>>>(x);
    ln_kernel<<<NTOK, 256>>>(gamma, beta, sw, sb);
    gram_mma_kernel<<<dim3(136, 1, BB), 256, GRAM_SMEM>>>();
    knn_kernel<<<NTOK, 256>>>(noise);
    distmin_kernel<<<NTOK, 256>>>();
    top2_kernel<<<BB, 256>>>();
    assign_kernel<<<NTOK / 256, 256>>>(out);
    weight_kernel<<<NTOK / 256, 256>>>(out);
    merge_kernel<<<dim3(CC / 256, 2, BB), 256>>>(out);
}

// round 14
// speedup vs baseline: 1.9691x; 1.0043x over previous
#include <cuda_runtime.h>
#include <cuda_fp16.h>
#include <math.h>
#include <stdint.h>

// Problem constants
#define BB 16
#define NN 2048
#define CC 768
#define NTOK (BB*NN)          // 32768
#define LN_EPS 1e-5f
#define RSQRT_C 0.03608439182435161f   // 1/sqrt(768)
#define WSCALE 256.0f
#define INV_WSCALE 0.00390625f

// fp16 smem tile geometry: one k16 chunk/row = 8 b32 words + 4 pad = 48B
#define WSTR 12
// conv stage buffer (words): A 128 rows hi+lo (3072), B 256 rows hi+lo (6144)
#define CA_LO (128*WSTR)          // 1536
#define CB_HI (128*WSTR*2)        // 3072
#define CB_LO (CB_HI + 256*WSTR)  // 6144
#define CBUF_W (128*WSTR*2 + 256*WSTR*2)      // 9216
#define CONV_SMEM (4*CBUF_W*4)                 // 147456 B, 4-stage pipeline
// gram stage buffer: A 128 + B 128 rows, hi+lo
#define GA_LO (128*WSTR)
#define GB_HI (256*WSTR)
#define GB_LO (256*WSTR + 128*WSTR)
#define GBUF_W (128*WSTR*2 + 128*WSTR*2)      // 6144
#define GSTG_PITCH 130
#define GRAM_SMEM (4*GBUF_W*4)                 // 98304 B (reused as fp32 staging)

// ---------------- scratch (device globals; no runtime alloc allowed) ----------
__device__ float  g_y[(size_t)NTOK * CC];          // conv+LN output (fp32, for merge)
__device__ float  g_dist[(size_t)NTOK * NN];       // 268 MB distance matrix
__device__ __half g_xh[(size_t)NTOK * CC];         // x split hi
__device__ __half g_xl[(size_t)NTOK * CC];         // x split lo
__device__ __half g_yh[(size_t)NTOK * CC];         // LN(y) split hi
__device__ __half g_yl[(size_t)NTOK * CC];         // LN(y) split lo
__device__ __half g_wh[3 * CC * CC];               // W*256 split hi  [k][co][ci]
__device__ __half g_wl[3 * CC * CC];               // W*256 split lo
__device__ float  g_sq[NTOK];
__device__ float  g_tw[NTOK];
__device__ float  g_density[NTOK];
__device__ float  g_score[NTOK];
__device__ float  g_distmax[BB];
__device__ int    g_idxdown[BB * 2];
__device__ float  g_allw[BB * 2];
__device__ int    g_cluster[NTOK];

// ---------------- helpers -------------------------------------------------------
__device__ __forceinline__ uint32_t smem_u32(const void* p) {
    uint32_t a;
    asm("{ .reg .u64 t; cvta.to.shared.u64 t, %1; cvt.u32.u64 %0, t; }" : "=r"(a) : "l"(p));
    return a;
}

__device__ __forceinline__ void mma16(float* d, const uint32_t* a, uint32_t b0, uint32_t b1) {
    asm volatile(
        "mma.sync.aligned.m16n8k16.row.col.f32.f16.f16.f32 "
        "{%0,%1,%2,%3},{%4,%5,%6,%7},{%8,%9},{%0,%1,%2,%3};"
        : "+f"(d[0]), "+f"(d[1]), "+f"(d[2]), "+f"(d[3])
        : "r"(a[0]), "r"(a[1]), "r"(a[2]), "r"(a[3]), "r"(b0), "r"(b1));
}

#define CP_ASYNC16(dst, src, sz) \
    asm volatile("cp.async.cg.shared.global [%0], [%1], 16, %2;" \
                 :: "r"(dst), "l"(src), "r"(sz) : "memory")
#define CP_COMMIT() asm volatile("cp.async.commit_group;" ::: "memory")
#define CP_WAIT2()  asm volatile("cp.async.wait_group 2;" ::: "memory")
#define CP_WAIT0()  asm volatile("cp.async.wait_group 0;" ::: "memory")

// 3xFP16 warp compute for one k16 stage. acc layout [MI*NI][4].
// Term loop hoisted between ni-block and mi: each accumulator's three
// emulation terms are separated by NB*MI independent mmas (breaks RAW chain).
// Per-acc summation order stays hh -> hl -> lh (numerics identical).
template<int MI, int NI, int NB>
__device__ __forceinline__ void mma_stage(const uint32_t* sah, const uint32_t* sal,
                                          const uint32_t* sbh, const uint32_t* sbl,
                                          float (*acc)[4], int mb, int nb, int kc) {
    uint32_t Ah[MI][4], Al[MI][4];
#pragma unroll
    for (int mi = 0; mi < MI; ++mi) {
        int off = (mb + mi * 16) * WSTR + kc;
        Ah[mi][0] = sah[off];            Ah[mi][1] = sah[off + 8 * WSTR];
        Ah[mi][2] = sah[off + 4];        Ah[mi][3] = sah[off + 8 * WSTR + 4];
        Al[mi][0] = sal[off];            Al[mi][1] = sal[off + 8 * WSTR];
        Al[mi][2] = sal[off + 4];        Al[mi][3] = sal[off + 8 * WSTR + 4];
    }
#pragma unroll
    for (int nB = 0; nB < NI / NB; ++nB) {
        uint32_t bh0[NB], bh1[NB], bl0[NB], bl1[NB];
#pragma unroll
        for (int j = 0; j < NB; ++j) {
            int off = (nb + (nB * NB + j) * 8) * WSTR + kc;
            bh0[j] = sbh[off]; bh1[j] = sbh[off + 4];
            bl0[j] = sbl[off]; bl1[j] = sbl[off + 4];
        }
#pragma unroll
        for (int j = 0; j < NB; ++j)
#pragma unroll
            for (int mi = 0; mi < MI; ++mi)
                mma16(acc[mi * NI + nB * NB + j], Ah[mi], bh0[j], bh1[j]);
#pragma unroll
        for (int j = 0; j < NB; ++j)
#pragma unroll
            for (int mi = 0; mi < MI; ++mi)
                mma16(acc[mi * NI + nB * NB + j], Ah[mi], bl0[j], bl1[j]);
#pragma unroll
        for (int j = 0; j < NB; ++j)
#pragma unroll
            for (int mi = 0; mi < MI; ++mi)
                mma16(acc[mi * NI + nB * NB + j], Al[mi], bh0[j], bh1[j]);
    }
}

// ---------------- prep kernels ---------------------------------------------------
__global__ void prep_x_kernel(const float* __restrict__ x) {
    size_t i = ((size_t)blockIdx.x * 256 + threadIdx.x) * 8;
    float4 a = *reinterpret_cast<const float4*>(x + i);
    float4 b = *reinterpret_cast<const float4*>(x + i + 4);
    __half h[8]; float v[8] = {a.x, a.y, a.z, a.w, b.x, b.y, b.z, b.w};
#pragma unroll
    for (int t = 0; t < 8; ++t) h[t] = __float2half_rn(v[t]);
    *reinterpret_cast<uint4*>(g_xh + i) = *reinterpret_cast<uint4*>(h);
#pragma unroll
    for (int t = 0; t < 8; ++t) h[t] = __float2half_rn(v[t] - __half2float(h[t]));
    *reinterpret_cast<uint4*>(g_xl + i) = *reinterpret_cast<uint4*>(h);
}

__global__ void repack_kernel(const float* __restrict__ w) {
    int i = blockIdx.x * 256 + threadIdx.x;     // over 768*768*3, w is [co][ci][k]
    if (i >= CC * CC * 3) return;
    int k  = i % 3;
    int ci = (i / 3) % CC;
    int co = i / (3 * CC);
    float v = w[i] * WSCALE;
    __half hi = __float2half_rn(v);
    size_t o = ((size_t)k * CC + co) * CC + ci;
    g_wh[o] = hi;
    g_wl[o] = __float2half_rn(v - __half2float(hi));
}

__global__ void init_kernel() {
    int t = threadIdx.x;
    if (t < BB) g_distmax[t] = 0.0f;
    if (t < BB * 2) g_allw[t] = 1e-6f;
}

// =============== 3xFP16 mma GEMM 1: residual conv ==============================
// CTA 128(m) x 256(n), K = 3*768 -> 144 k16 stages, 4-buffer cp.async pipeline,
// single __syncthreads per stage (wait -> sync -> issue -> compute).
__global__ __launch_bounds__(256, 1) void conv_mma_kernel(const float* __restrict__ x) {
    extern __shared__ uint32_t smw[];
    const int tid = threadIdx.x, w = tid >> 5, lane = tid & 31;
    const int co0 = blockIdx.x * 256;
    const int m0  = blockIdx.y * 128;
    const int bq  = m0 >> 11;
    const int nn0 = m0 & 2047;
    const uint32_t smbase = smem_u32(smw);

    // per-thread cp.async chunk descriptors (6 chunks of 16B per stage)
    int crow[6], cpart[6], chalf[6], cisB[6]; uint32_t cdst[6];
#pragma unroll
    for (int t = 0; t < 6; ++t) {
        int c = t * 256 + tid;
        int isB = c >= 512;
        int d = isB ? c - 512 : c;
        int row = d >> 2, part = (d >> 1) & 1, hf = d & 1;
        crow[t] = row; cpart[t] = part; chalf[t] = hf; cisB[t] = isB;
        cdst[t] = (uint32_t)((isB ? (CB_HI + part * 256 * WSTR)
                                  : (part * 128 * WSTR)) + row * WSTR + hf * 4) * 4;
    }

#define CONV_ISSUE(s) do { \
    int kk = (s) / 48, ci = (s) - kk * 48; \
    uint32_t sb = smbase + (((s) & 3) * CBUF_W) * 4; \
    _Pragma("unroll") \
    for (int t = 0; t < 6; ++t) { \
        const __half* src; int sz = 16; \
        if (!cisB[t]) { \
            int r = nn0 + crow[t] + kk - 1; \
            if (r < 0 || r >= NN) { sz = 0; r = 0; } \
            src = (cpart[t] ? g_xl : g_xh) + ((size_t)(bq * NN + r) * CC + ci * 16 + chalf[t] * 8); \
        } else { \
            src = (cpart[t] ? g_wl : g_wh) + (((size_t)kk * CC + co0 + crow[t]) * CC + ci * 16 + chalf[t] * 8); \
        } \
        CP_ASYNC16(sb + cdst[t], src, sz); \
    } \
    CP_COMMIT(); \
} while (0)

    float acc[32][4];
#pragma unroll
    for (int a = 0; a < 32; ++a)
#pragma unroll
        for (int c = 0; c < 4; ++c) acc[a][c] = 0.f;

    const int mb = (w >> 2) * 64 + (lane >> 2);
    const int nb = (w & 3) * 64 + (lane >> 2);
    const int kc = lane & 3;

    CONV_ISSUE(0); CONV_ISSUE(1); CONV_ISSUE(2);
    for (int s = 0; s < 144; ++s) {
        CP_WAIT2();
        __syncthreads();   // group s visible to all; all warps done with buffer (s-1)&3
        if (s + 3 < 144) { CONV_ISSUE(s + 3); } else { CP_COMMIT(); }
        const uint32_t* base = smw + (s & 3) * CBUF_W;
        mma_stage<4, 8, 1>(base, base + CA_LO, base + CB_HI, base + CB_LO,
                           acc, mb, nb, kc);
    }
#undef CONV_ISSUE

    // epilogue: residual add (undo weight pre-scale), float2 stores
    const int mbase = m0 + (w >> 2) * 64 + (lane >> 2);
    const int nbase = co0 + (w & 3) * 64 + (lane & 3) * 2;
#pragma unroll
    for (int mi = 0; mi < 4; ++mi) {
#pragma unroll
        for (int h = 0; h < 2; ++h) {
            int m = mbase + mi * 16 + h * 8;
            const float* xrow = x + (size_t)m * CC;
            float* yrow = g_y + (size_t)m * CC;
#pragma unroll
            for (int ni = 0; ni < 8; ++ni) {
                int c = nbase + ni * 8;
                float2 xv = *reinterpret_cast<const float2*>(xrow + c);
                float2 o;
                o.x = xv.x + acc[mi * 8 + ni][h * 2 + 0] * INV_WSCALE;
                o.y = xv.y + acc[mi * 8 + ni][h * 2 + 1] * INV_WSCALE;
                *reinterpret_cast<float2*>(yrow + c) = o;
            }
        }
    }
}

// =============== 3xFP16 mma GEMM 2: symmetric Gram + dist ======================
// 128x128 tiles, only jb>=ib; mirror-write off-diagonal. 4-buffer pipeline,
// single sync per stage.
__global__ __launch_bounds__(256, 1) void gram_mma_kernel() {
    extern __shared__ uint32_t smw[];
    const int tid = threadIdx.x, w = tid >> 5, lane = tid & 31;
    const int b = blockIdx.z;
    int idx = blockIdx.x, ib = 0;
    while (idx >= 16 - ib) { idx -= 16 - ib; ++ib; }
    const int jb = ib + idx;
    const int i0 = ib * 128, j0 = jb * 128;
    const uint32_t smbase = smem_u32(smw);

    // per-thread chunk descriptors (4 chunks per stage)
    int crow[4], cpart[4], chalf[4], cisB[4]; uint32_t cdst[4];
#pragma unroll
    for (int t = 0; t < 4; ++t) {
        int c = t * 256 + tid;
        int isB = c >= 512;
        int d = isB ? c - 512 : c;
        int row = d >> 2, part = (d >> 1) & 1, hf = d & 1;
        crow[t] = row; cpart[t] = part; chalf[t] = hf; cisB[t] = isB;
        cdst[t] = (uint32_t)((isB ? GB_HI : 0) + part * 128 * WSTR + row * WSTR + hf * 4) * 4;
    }

#define GRAM_ISSUE(s) do { \
    uint32_t sb = smbase + (((s) & 3) * GBUF_W) * 4; \
    _Pragma("unroll") \
    for (int t = 0; t < 4; ++t) { \
        int base0 = cisB[t] ? j0 : i0; \
        const __half* src = (cpart[t] ? g_yl : g_yh) + \
            ((size_t)(b * NN + base0 + crow[t]) * CC + (s) * 16 + chalf[t] * 8); \
        CP_ASYNC16(sb + cdst[t], src, 16); \
    } \
    CP_COMMIT(); \
} while (0)

    float acc[16][4];
#pragma unroll
    for (int a = 0; a < 16; ++a)
#pragma unroll
        for (int c = 0; c < 4; ++c) acc[a][c] = 0.f;

    const int mb = (w & 3) * 32 + (lane >> 2);
    const int nb = (w >> 2) * 64 + (lane >> 2);
    const int kc = lane & 3;

    GRAM_ISSUE(0); GRAM_ISSUE(1); GRAM_ISSUE(2);
    for (int s = 0; s < 48; ++s) {
        CP_WAIT2();
        __syncthreads();
        if (s + 3 < 48) { GRAM_ISSUE(s + 3); } else { CP_COMMIT(); }
        const uint32_t* base = smw + (s & 3) * GBUF_W;
        mma_stage<2, 8, 2>(base, base + GA_LO, base + GB_HI, base + GB_LO,
                           acc, mb, nb, kc);
    }
#undef GRAM_ISSUE
    CP_WAIT0();
    __syncthreads();

    // epilogue: dist into padded staging (reuse pipeline smem), then coalesced stores
    float* stg = reinterpret_cast<float*>(smw);
    const float* sqb = g_sq + b * NN;
    const int wm = w & 3, wn = w >> 2;
#pragma unroll
    for (int mi = 0; mi < 2; ++mi) {
#pragma unroll
        for (int c2 = 0; c2 < 2; ++c2) {
            int rr = wm * 32 + mi * 16 + (lane >> 2) + c2 * 8;
            float si = sqb[i0 + rr];
#pragma unroll
            for (int ni = 0; ni < 8; ++ni) {
#pragma unroll
                for (int c1 = 0; c1 < 2; ++c1) {
                    int cn = wn * 64 + ni * 8 + (lane & 3) * 2 + c1;
                    float g = acc[mi * 8 + ni][c2 * 2 + c1];
                    float d2 = si + sqb[j0 + cn] - 2.0f * g;
                    stg[rr * GSTG_PITCH + cn] = sqrtf(fmaxf(d2, 0.f)) * RSQRT_C;
                }
            }
        }
    }
    __syncthreads();
#pragma unroll
    for (int q = 0; q < 16; ++q) {
        int row = w * 16 + q;
        float2 v0 = *reinterpret_cast<const float2*>(stg + row * GSTG_PITCH + lane * 4);
        float2 v1 = *reinterpret_cast<const float2*>(stg + row * GSTG_PITCH + lane * 4 + 2);
        float4 o = make_float4(v0.x, v0.y, v1.x, v1.y);
        *reinterpret_cast<float4*>(g_dist + ((size_t)(b * NN + i0 + row)) * NN + j0 + lane * 4) = o;
    }
    if (ib != jb) {
#pragma unroll
        for (int q = 0; q < 16; ++q) {
            int col = w * 16 + q;
            float4 o;
            o.x = stg[(lane * 4 + 0) * GSTG_PITCH + col];
            o.y = stg[(lane * 4 + 1) * GSTG_PITCH + col];
            o.z = stg[(lane * 4 + 2) * GSTG_PITCH + col];
            o.w = stg[(lane * 4 + 3) * GSTG_PITCH + col];
            *reinterpret_cast<float4*>(g_dist + ((size_t)(b * NN + j0 + col)) * NN + i0 + lane * 4) = o;
        }
    }
}

// ---------------- LayerNorm + score + sq + fp16 split (shuffle reductions) -----
__global__ __launch_bounds__(256) void ln_kernel(const float* __restrict__ gamma,
                                                 const float* __restrict__ beta,
                                                 const float* __restrict__ sw,
                                                 const float* __restrict__ sbv) {
    __shared__ float red[16];
    __shared__ float bc[2];
    const int m = blockIdx.x;
    const int tid = threadIdx.x;
    const int w = tid >> 5, lane = tid & 31;
    float* yrow = g_y + (size_t)m * CC;

    float v0 = yrow[tid], v1 = yrow[tid + 256], v2 = yrow[tid + 512];
    float s = v0 + v1 + v2;
    float ss = v0 * v0 + v1 * v1 + v2 * v2;
#pragma unroll
    for (int o = 16; o; o >>= 1) {
        s  += __shfl_xor_sync(0xffffffffu, s, o);
        ss += __shfl_xor_sync(0xffffffffu, ss, o);
    }
    if (lane == 0) { red[w] = s; red[8 + w] = ss; }
    __syncthreads();
    if (tid < 32) {
        float a = (lane < 8) ? red[lane] : 0.f;
        float c = (lane < 8) ? red[8 + lane] : 0.f;
#pragma unroll
        for (int o = 4; o; o >>= 1) {
            a += __shfl_xor_sync(0xffffffffu, a, o);
            c += __shfl_xor_sync(0xffffffffu, c, o);
        }
        if (lane == 0) {
            float mu = a / (float)CC;
            float var = c / (float)CC - mu * mu;
            bc[0] = mu;
            bc[1] = 1.0f / sqrtf(var + LN_EPS);
        }
    }
    __syncthreads();
    float mu = bc[0], inv = bc[1];
    float x0 = (v0 - mu) * inv * gamma[tid]       + beta[tid];
    float x1 = (v1 - mu) * inv * gamma[tid + 256] + beta[tid + 256];
    float x2 = (v2 - mu) * inv * gamma[tid + 512] + beta[tid + 512];
    yrow[tid] = x0; yrow[tid + 256] = x1; yrow[tid + 512] = x2;

    // fp16 hi/lo split for gram GEMM
    __half* yh = g_yh + (size_t)m * CC;
    __half* yl = g_yl + (size_t)m * CC;
    __half h0 = __float2half_rn(x0), h1 = __float2half_rn(x1), h2 = __float2half_rn(x2);
    yh[tid] = h0; yh[tid + 256] = h1; yh[tid + 512] = h2;
    yl[tid]       = __float2half_rn(x0 - __half2float(h0));
    yl[tid + 256] = __float2half_rn(x1 - __half2float(h1));
    yl[tid + 512] = __float2half_rn(x2 - __half2float(h2));

    float p = x0 * sw[tid] + x1 * sw[tid + 256] + x2 * sw[tid + 512];
    float q = x0 * x0 + x1 * x1 + x2 * x2;
#pragma unroll
    for (int o = 16; o; o >>= 1) {
        p += __shfl_xor_sync(0xffffffffu, p, o);
        q += __shfl_xor_sync(0xffffffffu, q, o);
    }
    if (lane == 0) { red[w] = p; red[8 + w] = q; }
    __syncthreads();
    if (tid == 0) {
        float pt = 0.f, qt = 0.f;
#pragma unroll
        for (int i = 0; i < 8; ++i) { pt += red[i]; qt += red[8 + i]; }
        g_sq[m] = qt;
        g_tw[m] = expf(pt + sbv[0]);
    }
}

// ---------------- top-3 smallest per row -> density; row max -> dist_max -------
__global__ __launch_bounds__(256) void knn_kernel(const float* __restrict__ noise) {
    const int m = blockIdx.x;
    const int b = m >> 11;
    const float* drow = g_dist + (size_t)m * NN;
    const int tid = threadIdx.x;

    float t0 = 1e30f, t1 = 1e30f, t2 = 1e30f, mx = 0.f;
    for (int j = tid; j < NN; j += 256) {
        float v = drow[j];
        mx = fmaxf(mx, v);
        if (v < t2) {
            if (v < t1) { t2 = t1; if (v < t0) { t1 = t0; t0 = v; } else t1 = v; }
            else t2 = v;
        }
    }
#pragma unroll
    for (int o = 16; o > 0; o >>= 1) {
        float u0 = __shfl_down_sync(0xffffffffu, t0, o);
        float u1 = __shfl_down_sync(0xffffffffu, t1, o);
        float u2 = __shfl_down_sync(0xffffffffu, t2, o);
        float um = __shfl_down_sync(0xffffffffu, mx, o);
        mx = fmaxf(mx, um);
        if (u0 < t2) { if (u0 < t1) { t2 = t1; if (u0 < t0) { t1 = t0; t0 = u0; } else t1 = u0; } else t2 = u0; }
        if (u1 < t2) { if (u1 < t1) { t2 = t1; if (u1 < t0) { t1 = t0; t0 = u1; } else t1 = u1; } else t2 = u1; }
        if (u2 < t2) { if (u2 < t1) { t2 = t1; if (u2 < t0) { t1 = t0; t0 = u2; } else t1 = u2; } else t2 = u2; }
    }
    __shared__ float s0[8], s1[8], s2[8], smx[8];
    int wid = tid >> 5, lane = tid & 31;
    if (lane == 0) { s0[wid] = t0; s1[wid] = t1; s2[wid] = t2; smx[wid] = mx; }
    __syncthreads();
    if (tid < 32) {
        t0 = (tid < 8) ? s0[tid] : 1e30f;
        t1 = (tid < 8) ? s1[tid] : 1e30f;
        t2 = (tid < 8) ? s2[tid] : 1e30f;
        mx = (tid < 8) ? smx[tid] : 0.f;
#pragma unroll
        for (int o = 4; o > 0; o >>= 1) {
            float u0 = __shfl_down_sync(0xffffffffu, t0, o);
            float u1 = __shfl_down_sync(0xffffffffu, t1, o);
            float u2 = __shfl_down_sync(0xffffffffu, t2, o);
            float um = __shfl_down_sync(0xffffffffu, mx, o);
            mx = fmaxf(mx, um);
            if (u0 < t2) { if (u0 < t1) { t2 = t1; if (u0 < t0) { t1 = t0; t0 = u0; } else t1 = u0; } else t2 = u0; }
            if (u1 < t2) { if (u1 < t1) { t2 = t1; if (u1 < t0) { t1 = t0; t0 = u1; } else t1 = u1; } else t2 = u1; }
            if (u2 < t2) { if (u2 < t1) { t2 = t1; if (u2 < t0) { t1 = t0; t0 = u2; } else t1 = u2; } else t2 = u2; }
        }
        if (tid == 0) {
            float ds = (t0 * t0 + t1 * t1 + t2 * t2) / 3.0f;
            g_density[m] = expf(-ds) + noise[m] * 1e-6f;
            atomicMax((int*)(g_distmax + b), __float_as_int(mx));   // dist >= 0
        }
    }
}

// ---------------- dist_min to higher-density point; score ----------------------
__global__ __launch_bounds__(256) void distmin_kernel() {
    __shared__ float dens[NN];
    __shared__ float red[256];
    const int m = blockIdx.x;
    const int b = m >> 11;
    const int tid = threadIdx.x;
    const float* db = g_density + b * NN;
    for (int j = tid; j < NN; j += 256) dens[j] = db[j];
    __syncthreads();

    const float di   = dens[m & 2047];
    const float dmax = g_distmax[b];
    const float* drow = g_dist + (size_t)m * NN;

    float mn = dmax;
    for (int j = tid; j < NN; j += 256) {
        float c = (dens[j] > di) ? drow[j] : dmax;
        mn = fminf(mn, c);
    }
    red[tid] = mn; __syncthreads();
    for (int o = 128; o; o >>= 1) { if (tid < o) red[tid] = fminf(red[tid], red[tid + o]); __syncthreads(); }
    if (tid == 0) g_score[m] = red[0] * di;
}

// ---------------- per-batch top-2 of score (lax.top_k tie: lower index) --------
__global__ __launch_bounds__(256) void top2_kernel() {
    __shared__ float sv[256];
    __shared__ int   si[256];
    const int b = blockIdx.x, tid = threadIdx.x;
    const float* sc = g_score + b * NN;

    float bv = -1e30f; int bi = 1 << 30;
    for (int j = tid; j < NN; j += 256) {
        float v = sc[j];
        if (v > bv || (v == bv && j < bi)) { bv = v; bi = j; }
    }
    sv[tid] = bv; si[tid] = bi; __syncthreads();
    for (int o = 128; o; o >>= 1) {
        if (tid < o) {
            float ov = sv[tid + o]; int oi = si[tid + o];
            if (ov > sv[tid] || (ov == sv[tid] && oi < si[tid])) { sv[tid] = ov; si[tid] = oi; }
        }
        __syncthreads();
    }
    int i0 = si[0];
    __syncthreads();

    bv = -1e30f; bi = 1 << 30;
    for (int j = tid; j < NN; j += 256) {
        if (j == i0) continue;
        float v = sc[j];
        if (v > bv || (v == bv && j < bi)) { bv = v; bi = j; }
    }
    sv[tid] = bv; si[tid] = bi; __syncthreads();
    for (int o = 128; o; o >>= 1) {
        if (tid < o) {
            float ov = sv[tid + o]; int oi = si[tid + o];
            if (ov > sv[tid] || (ov == sv[tid] && oi < si[tid])) { sv[tid] = ov; si[tid] = oi; }
        }
        __syncthreads();
    }
    if (tid == 0) { g_idxdown[b * 2] = i0; g_idxdown[b * 2 + 1] = si[0]; }
}

// ---------------- cluster assignment + all_weight accumulation ------------------
__global__ void assign_kernel(float* __restrict__ out) {
    int m = blockIdx.x * 256 + threadIdx.x;
    if (m >= NTOK) return;
    int b = m >> 11, n = m & 2047;
    int i0 = g_idxdown[b * 2], i1 = g_idxdown[b * 2 + 1];
    float d0 = g_dist[((size_t)(b * NN + i0)) * NN + n];
    float d1 = g_dist[((size_t)(b * NN + i1)) * NN + n];
    int cl = (d0 <= d1) ? 0 : 1;   // argmin tie -> first
    if (n == i0) cl = 0;
    if (n == i1) cl = 1;
    g_cluster[m] = cl;
    out[24576 + 32768 + m] = (float)cl;        // idx_cluster region (as float)
    atomicAdd(&g_allw[b * 2 + cl], g_tw[m]);
}

// ---------------- normalized weight output --------------------------------------
__global__ void weight_kernel(float* __restrict__ out) {
    int m = blockIdx.x * 256 + threadIdx.x;
    if (m >= NTOK) return;
    int b = m >> 11;
    float nw = g_tw[m] / g_allw[b * 2 + g_cluster[m]];
    out[24576 + m] = nw;                        // agg_weight_new region
}

// ---------------- weighted merge x_merged[b,k,:] ---------------------------------
__global__ __launch_bounds__(256) void merge_kernel(float* __restrict__ out) {
    __shared__ float wgt[NN];
    const int k = blockIdx.y, b = blockIdx.z;
    const int tid = threadIdx.x;
    const int c = blockIdx.x * 256 + tid;
    const float aw = g_allw[b * 2 + k];
    const int*   cl = g_cluster + b * NN;
    const float* tw = g_tw + b * NN;
    for (int j = tid; j < NN; j += 256)
        wgt[j] = (cl[j] == k) ? (tw[j] / aw) : 0.0f;
    __syncthreads();
    const float* xb = g_y + (size_t)b * NN * CC;
    float acc = 0.f;
    for (int n = 0; n < NN; ++n)
        acc = fmaf(xb[(size_t)n * CC + c], wgt[n], acc);
    out[(size_t)(b * 2 + k) * CC + c] = acc;    // x_merged region
}

// ---------------- launch --------------------------------------------------------
extern "C" void kernel_launch(void* const* d_in, const int* in_sizes, int n_in,
                              void* d_out, int out_size) {
    const float* x      = (const float*)d_in[0];
    const float* conv_w = (const float*)d_in[1];
    const float* gamma  = (const float*)d_in[2];
    const float* beta   = (const float*)d_in[3];
    const float* sw     = (const float*)d_in[4];
    const float* sb     = (const float*)d_in[5];
    const float* noise  = (const float*)d_in[6];
    float* out = (float*)d_out;

    cudaFuncSetAttribute(conv_mma_kernel, cudaFuncAttributeMaxDynamicSharedMemorySize, CONV_SMEM);
    cudaFuncSetAttribute(gram_mma_kernel, cudaFuncAttributeMaxDynamicSharedMemorySize, GRAM_SMEM);

    repack_kernel<<<(CC * CC * 3 + 255) / 256, 256>>>(conv_w);
    prep_x_kernel<<<(NTOK * CC / 8) / 256, 256>>>(x);
    init_kernel<<<1, 32>>>();
    conv_mma_kernel<<<dim3(CC / 256, NTOK / 128), 256, CONV_SMEM>>>(x);
    ln_kernel<<<NTOK, 256>>>(gamma, beta, sw, sb);
    gram_mma_kernel<<<dim3(136, 1, BB), 256, GRAM_SMEM>>>();
    knn_kernel<<<NTOK, 256>>>(noise);
    distmin_kernel<<<NTOK, 256>>>();
    top2_kernel<<<BB, 256>>>();
    assign_kernel<<<NTOK / 256, 256>>>(out);
    weight_kernel<<<NTOK / 256, 256>>>(out);
    merge_kernel<<<dim3(CC / 256, 2, BB), 256>>>(out);
}

// round 17
// speedup vs baseline: 2.2615x; 1.1485x over previous
#include <cuda_runtime.h>
#include <cuda_fp16.h>
#include <math.h>
#include <stdint.h>

// Problem constants
#define BB 16
#define NN 2048
#define CC 768
#define NTOK (BB*NN)          // 32768
#define LN_EPS 1e-5f
#define RSQRT_C 0.03608439182435161f   // 1/sqrt(768)
#define WSCALE 256.0f
#define INV_WSCALE 0.00390625f

// fp16 smem tile geometry: one k16 chunk/row = 8 b32 words + 4 pad = 48B
#define WSTR 12
// stage buffer (words): A 128 rows hi+lo (3072) + B 128 rows hi+lo (3072)
#define T_LO (128*WSTR)            // 1536
#define T_BHI (128*WSTR*2)         // 3072
#define T_BLO (T_BHI + 128*WSTR)   // 4608
#define TBUF_W (128*WSTR*4)        // 6144 words = 24KB
#define GEMM_SMEM (4*TBUF_W*4)     // 98304 B, 4-stage pipeline, 2 CTAs/SM
#define GSTG_PITCH 130

// ---------------- scratch (device globals; no runtime alloc allowed) ----------
__device__ float  g_y[(size_t)NTOK * CC];          // conv+LN output (fp32, for merge)
__device__ float  g_dist[(size_t)NTOK * NN];       // 268 MB distance matrix
__device__ __half g_xh[(size_t)NTOK * CC];         // x split hi
__device__ __half g_xl[(size_t)NTOK * CC];         // x split lo
__device__ __half g_yh[(size_t)NTOK * CC];         // LN(y) split hi
__device__ __half g_yl[(size_t)NTOK * CC];         // LN(y) split lo
__device__ __half g_wh[3 * CC * CC];               // W*256 split hi  [k][co][ci]
__device__ __half g_wl[3 * CC * CC];               // W*256 split lo
__device__ float  g_sq[NTOK];
__device__ float  g_tw[NTOK];
__device__ float  g_density[NTOK];
__device__ float  g_score[NTOK];
__device__ float  g_distmax[BB];
__device__ int    g_idxdown[BB * 2];
__device__ float  g_allw[BB * 2];
__device__ int    g_cluster[NTOK];

// ---------------- helpers -------------------------------------------------------
__device__ __forceinline__ uint32_t smem_u32(const void* p) {
    uint32_t a;
    asm("{ .reg .u64 t; cvta.to.shared.u64 t, %1; cvt.u32.u64 %0, t; }" : "=r"(a) : "l"(p));
    return a;
}

__device__ __forceinline__ void mma16(float* d, const uint32_t* a, uint32_t b0, uint32_t b1) {
    asm volatile(
        "mma.sync.aligned.m16n8k16.row.col.f32.f16.f16.f32 "
        "{%0,%1,%2,%3},{%4,%5,%6,%7},{%8,%9},{%0,%1,%2,%3};"
        : "+f"(d[0]), "+f"(d[1]), "+f"(d[2]), "+f"(d[3])
        : "r"(a[0]), "r"(a[1]), "r"(a[2]), "r"(a[3]), "r"(b0), "r"(b1));
}

#define CP_ASYNC16(dst, src, sz) \
    asm volatile("cp.async.cg.shared.global [%0], [%1], 16, %2;" \
                 :: "r"(dst), "l"(src), "r"(sz) : "memory")
#define CP_COMMIT() asm volatile("cp.async.commit_group;" ::: "memory")
#define CP_WAIT2()  asm volatile("cp.async.wait_group 2;" ::: "memory")
#define CP_WAIT0()  asm volatile("cp.async.wait_group 0;" ::: "memory")

// 3xFP16 warp compute for one k16 stage, warp tile 32x64 (MI=2, NI=8).
// Per-acc summation order hh -> hl -> lh (numerics identical to prior rounds).
__device__ __forceinline__ void mma_stage(const uint32_t* sah, const uint32_t* sal,
                                          const uint32_t* sbh, const uint32_t* sbl,
                                          float (*acc)[4], int mb, int nb, int kc) {
    uint32_t Ah[2][4], Al[2][4];
#pragma unroll
    for (int mi = 0; mi < 2; ++mi) {
        int off = (mb + mi * 16) * WSTR + kc;
        Ah[mi][0] = sah[off];            Ah[mi][1] = sah[off + 8 * WSTR];
        Ah[mi][2] = sah[off + 4];        Ah[mi][3] = sah[off + 8 * WSTR + 4];
        Al[mi][0] = sal[off];            Al[mi][1] = sal[off + 8 * WSTR];
        Al[mi][2] = sal[off + 4];        Al[mi][3] = sal[off + 8 * WSTR + 4];
    }
#pragma unroll
    for (int nB = 0; nB < 4; ++nB) {
        uint32_t bh0[2], bh1[2], bl0[2], bl1[2];
#pragma unroll
        for (int j = 0; j < 2; ++j) {
            int off = (nb + (nB * 2 + j) * 8) * WSTR + kc;
            bh0[j] = sbh[off]; bh1[j] = sbh[off + 4];
            bl0[j] = sbl[off]; bl1[j] = sbl[off + 4];
        }
#pragma unroll
        for (int j = 0; j < 2; ++j)
#pragma unroll
            for (int mi = 0; mi < 2; ++mi)
                mma16(acc[mi * 8 + nB * 2 + j], Ah[mi], bh0[j], bh1[j]);
#pragma unroll
        for (int j = 0; j < 2; ++j)
#pragma unroll
            for (int mi = 0; mi < 2; ++mi)
                mma16(acc[mi * 8 + nB * 2 + j], Ah[mi], bl0[j], bl1[j]);
#pragma unroll
        for (int j = 0; j < 2; ++j)
#pragma unroll
            for (int mi = 0; mi < 2; ++mi)
                mma16(acc[mi * 8 + nB * 2 + j], Al[mi], bh0[j], bh1[j]);
    }
}

// ---------------- prep kernels ---------------------------------------------------
__global__ void prep_x_kernel(const float* __restrict__ x) {
    size_t i = ((size_t)blockIdx.x * 256 + threadIdx.x) * 8;
    float4 a = *reinterpret_cast<const float4*>(x + i);
    float4 b = *reinterpret_cast<const float4*>(x + i + 4);
    __half h[8]; float v[8] = {a.x, a.y, a.z, a.w, b.x, b.y, b.z, b.w};
#pragma unroll
    for (int t = 0; t < 8; ++t) h[t] = __float2half_rn(v[t]);
    *reinterpret_cast<uint4*>(g_xh + i) = *reinterpret_cast<uint4*>(h);
#pragma unroll
    for (int t = 0; t < 8; ++t) h[t] = __float2half_rn(v[t] - __half2float(h[t]));
    *reinterpret_cast<uint4*>(g_xl + i) = *reinterpret_cast<uint4*>(h);
}

__global__ void repack_kernel(const float* __restrict__ w) {
    int i = blockIdx.x * 256 + threadIdx.x;     // over 768*768*3, w is [co][ci][k]
    if (i >= CC * CC * 3) return;
    int k  = i % 3;
    int ci = (i / 3) % CC;
    int co = i / (3 * CC);
    float v = w[i] * WSCALE;
    __half hi = __float2half_rn(v);
    size_t o = ((size_t)k * CC + co) * CC + ci;
    g_wh[o] = hi;
    g_wl[o] = __float2half_rn(v - __half2float(hi));
}

__global__ void init_kernel() {
    int t = threadIdx.x;
    if (t < BB) g_distmax[t] = 0.0f;
    if (t < BB * 2) g_allw[t] = 1e-6f;
}

// =============== 3xFP16 mma GEMM 1: residual conv ==============================
// CTA 128(m) x 128(n), warp tile 32x64, K = 3*768 -> 144 k16 stages,
// 4-buffer cp.async pipeline, 2 CTAs/SM.
__global__ __launch_bounds__(256, 2) void conv_mma_kernel(const float* __restrict__ x) {
    extern __shared__ uint32_t smw[];
    const int tid = threadIdx.x, w = tid >> 5, lane = tid & 31;
    const int co0 = blockIdx.x * 128;
    const int m0  = blockIdx.y * 128;
    const int bq  = m0 >> 11;
    const int nn0 = m0 & 2047;
    const uint32_t smbase = smem_u32(smw);

    // per-thread cp.async chunk descriptors (4 chunks of 16B per stage)
    int crow[4], cpart[4], chalf[4], cisB[4]; uint32_t cdst[4];
#pragma unroll
    for (int t = 0; t < 4; ++t) {
        int c = t * 256 + tid;
        int isB = c >= 512;
        int d = c & 511;
        int row = d >> 2, part = (d >> 1) & 1, hf = d & 1;
        crow[t] = row; cpart[t] = part; chalf[t] = hf; cisB[t] = isB;
        cdst[t] = (uint32_t)((isB ? T_BHI : 0) + part * 128 * WSTR + row * WSTR + hf * 4) * 4;
    }

#define CONV_ISSUE(s) do { \
    int kk = (s) / 48, ci = (s) - kk * 48; \
    uint32_t sb = smbase + (((s) & 3) * TBUF_W) * 4; \
    _Pragma("unroll") \
    for (int t = 0; t < 4; ++t) { \
        const __half* src; int sz = 16; \
        if (!cisB[t]) { \
            int r = nn0 + crow[t] + kk - 1; \
            if (r < 0 || r >= NN) { sz = 0; r = 0; } \
            src = (cpart[t] ? g_xl : g_xh) + ((size_t)(bq * NN + r) * CC + ci * 16 + chalf[t] * 8); \
        } else { \
            src = (cpart[t] ? g_wl : g_wh) + (((size_t)kk * CC + co0 + crow[t]) * CC + ci * 16 + chalf[t] * 8); \
        } \
        CP_ASYNC16(sb + cdst[t], src, sz); \
    } \
    CP_COMMIT(); \
} while (0)

    float acc[16][4];
#pragma unroll
    for (int a = 0; a < 16; ++a)
#pragma unroll
        for (int c = 0; c < 4; ++c) acc[a][c] = 0.f;

    const int mb = (w & 3) * 32 + (lane >> 2);
    const int nb = (w >> 2) * 64 + (lane >> 2);
    const int kc = lane & 3;

    CONV_ISSUE(0); CONV_ISSUE(1); CONV_ISSUE(2);
    for (int s = 0; s < 144; ++s) {
        CP_WAIT2();
        __syncthreads();
        if (s + 3 < 144) { CONV_ISSUE(s + 3); } else { CP_COMMIT(); }
        const uint32_t* base = smw + (s & 3) * TBUF_W;
        mma_stage(base, base + T_LO, base + T_BHI, base + T_BLO, acc, mb, nb, kc);
    }
#undef CONV_ISSUE

    // epilogue: residual add (undo weight pre-scale), float2 stores
    const int mbase = m0 + (w & 3) * 32 + (lane >> 2);
    const int nbase = co0 + (w >> 2) * 64 + (lane & 3) * 2;
#pragma unroll
    for (int mi = 0; mi < 2; ++mi) {
#pragma unroll
        for (int h = 0; h < 2; ++h) {
            int m = mbase + mi * 16 + h * 8;
            const float* xrow = x + (size_t)m * CC;
            float* yrow = g_y + (size_t)m * CC;
#pragma unroll
            for (int ni = 0; ni < 8; ++ni) {
                int c = nbase + ni * 8;
                float2 xv = *reinterpret_cast<const float2*>(xrow + c);
                float2 o;
                o.x = xv.x + acc[mi * 8 + ni][h * 2 + 0] * INV_WSCALE;
                o.y = xv.y + acc[mi * 8 + ni][h * 2 + 1] * INV_WSCALE;
                *reinterpret_cast<float2*>(yrow + c) = o;
            }
        }
    }
}

// =============== 3xFP16 mma GEMM 2: symmetric Gram + dist ======================
// 128x128 tiles, only jb>=ib; mirror-write off-diagonal. 4-buffer pipeline,
// 2 CTAs/SM.
__global__ __launch_bounds__(256, 2) void gram_mma_kernel() {
    extern __shared__ uint32_t smw[];
    const int tid = threadIdx.x, w = tid >> 5, lane = tid & 31;
    const int b = blockIdx.z;
    int idx = blockIdx.x, ib = 0;
    while (idx >= 16 - ib) { idx -= 16 - ib; ++ib; }
    const int jb = ib + idx;
    const int i0 = ib * 128, j0 = jb * 128;
    const uint32_t smbase = smem_u32(smw);

    // per-thread chunk descriptors (4 chunks per stage)
    int crow[4], cpart[4], chalf[4], cisB[4]; uint32_t cdst[4];
#pragma unroll
    for (int t = 0; t < 4; ++t) {
        int c = t * 256 + tid;
        int isB = c >= 512;
        int d = c & 511;
        int row = d >> 2, part = (d >> 1) & 1, hf = d & 1;
        crow[t] = row; cpart[t] = part; chalf[t] = hf; cisB[t] = isB;
        cdst[t] = (uint32_t)((isB ? T_BHI : 0) + part * 128 * WSTR + row * WSTR + hf * 4) * 4;
    }

#define GRAM_ISSUE(s) do { \
    uint32_t sb = smbase + (((s) & 3) * TBUF_W) * 4; \
    _Pragma("unroll") \
    for (int t = 0; t < 4; ++t) { \
        int base0 = cisB[t] ? j0 : i0; \
        const __half* src = (cpart[t] ? g_yl : g_yh) + \
            ((size_t)(b * NN + base0 + crow[t]) * CC + (s) * 16 + chalf[t] * 8); \
        CP_ASYNC16(sb + cdst[t], src, 16); \
    } \
    CP_COMMIT(); \
} while (0)

    float acc[16][4];
#pragma unroll
    for (int a = 0; a < 16; ++a)
#pragma unroll
        for (int c = 0; c < 4; ++c) acc[a][c] = 0.f;

    const int mb = (w & 3) * 32 + (lane >> 2);
    const int nb = (w >> 2) * 64 + (lane >> 2);
    const int kc = lane & 3;

    GRAM_ISSUE(0); GRAM_ISSUE(1); GRAM_ISSUE(2);
    for (int s = 0; s < 48; ++s) {
        CP_WAIT2();
        __syncthreads();
        if (s + 3 < 48) { GRAM_ISSUE(s + 3); } else { CP_COMMIT(); }
        const uint32_t* base = smw + (s & 3) * TBUF_W;
        mma_stage(base, base + T_LO, base + T_BHI, base + T_BLO, acc, mb, nb, kc);
    }
#undef GRAM_ISSUE
    CP_WAIT0();
    __syncthreads();

    // epilogue: dist into padded staging (reuse pipeline smem), then coalesced stores
    float* stg = reinterpret_cast<float*>(smw);
    const float* sqb = g_sq + b * NN;
    const int wm = w & 3, wn = w >> 2;
#pragma unroll
    for (int mi = 0; mi < 2; ++mi) {
#pragma unroll
        for (int c2 = 0; c2 < 2; ++c2) {
            int rr = wm * 32 + mi * 16 + (lane >> 2) + c2 * 8;
            float si = sqb[i0 + rr];
#pragma unroll
            for (int ni = 0; ni < 8; ++ni) {
#pragma unroll
                for (int c1 = 0; c1 < 2; ++c1) {
                    int cn = wn * 64 + ni * 8 + (lane & 3) * 2 + c1;
                    float g = acc[mi * 8 + ni][c2 * 2 + c1];
                    float d2 = si + sqb[j0 + cn] - 2.0f * g;
                    stg[rr * GSTG_PITCH + cn] = sqrtf(fmaxf(d2, 0.f)) * RSQRT_C;
                }
            }
        }
    }
    __syncthreads();
#pragma unroll
    for (int q = 0; q < 16; ++q) {
        int row = w * 16 + q;
        float2 v0 = *reinterpret_cast<const float2*>(stg + row * GSTG_PITCH + lane * 4);
        float2 v1 = *reinterpret_cast<const float2*>(stg + row * GSTG_PITCH + lane * 4 + 2);
        float4 o = make_float4(v0.x, v0.y, v1.x, v1.y);
        *reinterpret_cast<float4*>(g_dist + ((size_t)(b * NN + i0 + row)) * NN + j0 + lane * 4) = o;
    }
    if (ib != jb) {
#pragma unroll
        for (int q = 0; q < 16; ++q) {
            int col = w * 16 + q;
            float4 o;
            o.x = stg[(lane * 4 + 0) * GSTG_PITCH + col];
            o.y = stg[(lane * 4 + 1) * GSTG_PITCH + col];
            o.z = stg[(lane * 4 + 2) * GSTG_PITCH + col];
            o.w = stg[(lane * 4 + 3) * GSTG_PITCH + col];
            *reinterpret_cast<float4*>(g_dist + ((size_t)(b * NN + j0 + col)) * NN + i0 + lane * 4) = o;
        }
    }
}

// ---------------- LayerNorm + score + sq + fp16 split (shuffle reductions) -----
__global__ __launch_bounds__(256) void ln_kernel(const float* __restrict__ gamma,
                                                 const float* __restrict__ beta,
                                                 const float* __restrict__ sw,
                                                 const float* __restrict__ sbv) {
    __shared__ float red[16];
    __shared__ float bc[2];
    const int m = blockIdx.x;
    const int tid = threadIdx.x;
    const int w = tid >> 5, lane = tid & 31;
    float* yrow = g_y + (size_t)m * CC;

    float v0 = yrow[tid], v1 = yrow[tid + 256], v2 = yrow[tid + 512];
    float s = v0 + v1 + v2;
    float ss = v0 * v0 + v1 * v1 + v2 * v2;
#pragma unroll
    for (int o = 16; o; o >>= 1) {
        s  += __shfl_xor_sync(0xffffffffu, s, o);
        ss += __shfl_xor_sync(0xffffffffu, ss, o);
    }
    if (lane == 0) { red[w] = s; red[8 + w] = ss; }
    __syncthreads();
    if (tid < 32) {
        float a = (lane < 8) ? red[lane] : 0.f;
        float c = (lane < 8) ? red[8 + lane] : 0.f;
#pragma unroll
        for (int o = 4; o; o >>= 1) {
            a += __shfl_xor_sync(0xffffffffu, a, o);
            c += __shfl_xor_sync(0xffffffffu, c, o);
        }
        if (lane == 0) {
            float mu = a / (float)CC;
            float var = c / (float)CC - mu * mu;
            bc[0] = mu;
            bc[1] = 1.0f / sqrtf(var + LN_EPS);
        }
    }
    __syncthreads();
    float mu = bc[0], inv = bc[1];
    float x0 = (v0 - mu) * inv * gamma[tid]       + beta[tid];
    float x1 = (v1 - mu) * inv * gamma[tid + 256] + beta[tid + 256];
    float x2 = (v2 - mu) * inv * gamma[tid + 512] + beta[tid + 512];
    yrow[tid] = x0; yrow[tid + 256] = x1; yrow[tid + 512] = x2;

    // fp16 hi/lo split for gram GEMM
    __half* yh = g_yh + (size_t)m * CC;
    __half* yl = g_yl + (size_t)m * CC;
    __half h0 = __float2half_rn(x0), h1 = __float2half_rn(x1), h2 = __float2half_rn(x2);
    yh[tid] = h0; yh[tid + 256] = h1; yh[tid + 512] = h2;
    yl[tid]       = __float2half_rn(x0 - __half2float(h0));
    yl[tid + 256] = __float2half_rn(x1 - __half2float(h1));
    yl[tid + 512] = __float2half_rn(x2 - __half2float(h2));

    float p = x0 * sw[tid] + x1 * sw[tid + 256] + x2 * sw[tid + 512];
    float q = x0 * x0 + x1 * x1 + x2 * x2;
#pragma unroll
    for (int o = 16; o; o >>= 1) {
        p += __shfl_xor_sync(0xffffffffu, p, o);
        q += __shfl_xor_sync(0xffffffffu, q, o);
    }
    if (lane == 0) { red[w] = p; red[8 + w] = q; }
    __syncthreads();
    if (tid == 0) {
        float pt = 0.f, qt = 0.f;
#pragma unroll
        for (int i = 0; i < 8; ++i) { pt += red[i]; qt += red[8 + i]; }
        g_sq[m] = qt;
        g_tw[m] = expf(pt + sbv[0]);
    }
}

// ---------------- top-3 smallest per row -> density; row max -> dist_max -------
__global__ __launch_bounds__(256) void knn_kernel(const float* __restrict__ noise) {
    const int m = blockIdx.x;
    const int b = m >> 11;
    const float* drow = g_dist + (size_t)m * NN;
    const int tid = threadIdx.x;

    float t0 = 1e30f, t1 = 1e30f, t2 = 1e30f, mx = 0.f;
    for (int j = tid; j < NN; j += 256) {
        float v = drow[j];
        mx = fmaxf(mx, v);
        if (v < t2) {
            if (v < t1) { t2 = t1; if (v < t0) { t1 = t0; t0 = v; } else t1 = v; }
            else t2 = v;
        }
    }
#pragma unroll
    for (int o = 16; o > 0; o >>= 1) {
        float u0 = __shfl_down_sync(0xffffffffu, t0, o);
        float u1 = __shfl_down_sync(0xffffffffu, t1, o);
        float u2 = __shfl_down_sync(0xffffffffu, t2, o);
        float um = __shfl_down_sync(0xffffffffu, mx, o);
        mx = fmaxf(mx, um);
        if (u0 < t2) { if (u0 < t1) { t2 = t1; if (u0 < t0) { t1 = t0; t0 = u0; } else t1 = u0; } else t2 = u0; }
        if (u1 < t2) { if (u1 < t1) { t2 = t1; if (u1 < t0) { t1 = t0; t0 = u1; } else t1 = u1; } else t2 = u1; }
        if (u2 < t2) { if (u2 < t1) { t2 = t1; if (u2 < t0) { t1 = t0; t0 = u2; } else t1 = u2; } else t2 = u2; }
    }
    __shared__ float s0[8], s1[8], s2[8], smx[8];
    int wid = tid >> 5, lane = tid & 31;
    if (lane == 0) { s0[wid] = t0; s1[wid] = t1; s2[wid] = t2; smx[wid] = mx; }
    __syncthreads();
    if (tid < 32) {
        t0 = (tid < 8) ? s0[tid] : 1e30f;
        t1 = (tid < 8) ? s1[tid] : 1e30f;
        t2 = (tid < 8) ? s2[tid] : 1e30f;
        mx = (tid < 8) ? smx[tid] : 0.f;
#pragma unroll
        for (int o = 4; o > 0; o >>= 1) {
            float u0 = __shfl_down_sync(0xffffffffu, t0, o);
            float u1 = __shfl_down_sync(0xffffffffu, t1, o);
            float u2 = __shfl_down_sync(0xffffffffu, t2, o);
            float um = __shfl_down_sync(0xffffffffu, mx, o);
            mx = fmaxf(mx, um);
            if (u0 < t2) { if (u0 < t1) { t2 = t1; if (u0 < t0) { t1 = t0; t0 = u0; } else t1 = u0; } else t2 = u0; }
            if (u1 < t2) { if (u1 < t1) { t2 = t1; if (u1 < t0) { t1 = t0; t0 = u1; } else t1 = u1; } else t2 = u1; }
            if (u2 < t2) { if (u2 < t1) { t2 = t1; if (u2 < t0) { t1 = t0; t0 = u2; } else t1 = u2; } else t2 = u2; }
        }
        if (tid == 0) {
            float ds = (t0 * t0 + t1 * t1 + t2 * t2) / 3.0f;
            g_density[m] = expf(-ds) + noise[m] * 1e-6f;
            atomicMax((int*)(g_distmax + b), __float_as_int(mx));   // dist >= 0
        }
    }
}

// ---------------- dist_min to higher-density point; score ----------------------
__global__ __launch_bounds__(256) void distmin_kernel() {
    __shared__ float dens[NN];
    __shared__ float red[256];
    const int m = blockIdx.x;
    const int b = m >> 11;
    const int tid = threadIdx.x;
    const float* db = g_density + b * NN;
    for (int j = tid; j < NN; j += 256) dens[j] = db[j];
    __syncthreads();

    const float di   = dens[m & 2047];
    const float dmax = g_distmax[b];
    const float* drow = g_dist + (size_t)m * NN;

    float mn = dmax;
    for (int j = tid; j < NN; j += 256) {
        float c = (dens[j] > di) ? drow[j] : dmax;
        mn = fminf(mn, c);
    }
    red[tid] = mn; __syncthreads();
    for (int o = 128; o; o >>= 1) { if (tid < o) red[tid] = fminf(red[tid], red[tid + o]); __syncthreads(); }
    if (tid == 0) g_score[m] = red[0] * di;
}

// ---------------- per-batch top-2 of score (lax.top_k tie: lower index) --------
__global__ __launch_bounds__(256) void top2_kernel() {
    __shared__ float sv[256];
    __shared__ int   si[256];
    const int b = blockIdx.x, tid = threadIdx.x;
    const float* sc = g_score + b * NN;

    float bv = -1e30f; int bi = 1 << 30;
    for (int j = tid; j < NN; j += 256) {
        float v = sc[j];
        if (v > bv || (v == bv && j < bi)) { bv = v; bi = j; }
    }
    sv[tid] = bv; si[tid] = bi; __syncthreads();
    for (int o = 128; o; o >>= 1) {
        if (tid < o) {
            float ov = sv[tid + o]; int oi = si[tid + o];
            if (ov > sv[tid] || (ov == sv[tid] && oi < si[tid])) { sv[tid] = ov; si[tid] = oi; }
        }
        __syncthreads();
    }
    int i0 = si[0];
    __syncthreads();

    bv = -1e30f; bi = 1 << 30;
    for (int j = tid; j < NN; j += 256) {
        if (j == i0) continue;
        float v = sc[j];
        if (v > bv || (v == bv && j < bi)) { bv = v; bi = j; }
    }
    sv[tid] = bv; si[tid] = bi; __syncthreads();
    for (int o = 128; o; o >>= 1) {
        if (tid < o) {
            float ov = sv[tid + o]; int oi = si[tid + o];
            if (ov > sv[tid] || (ov == sv[tid] && oi < si[tid])) { sv[tid] = ov; si[tid] = oi; }
        }
        __syncthreads();
    }
    if (tid == 0) { g_idxdown[b * 2] = i0; g_idxdown[b * 2 + 1] = si[0]; }
}

// ---------------- cluster assignment + all_weight accumulation ------------------
__global__ void assign_kernel(float* __restrict__ out) {
    int m = blockIdx.x * 256 + threadIdx.x;
    if (m >= NTOK) return;
    int b = m >> 11, n = m & 2047;
    int i0 = g_idxdown[b * 2], i1 = g_idxdown[b * 2 + 1];
    float d0 = g_dist[((size_t)(b * NN + i0)) * NN + n];
    float d1 = g_dist[((size_t)(b * NN + i1)) * NN + n];
    int cl = (d0 <= d1) ? 0 : 1;   // argmin tie -> first
    if (n == i0) cl = 0;
    if (n == i1) cl = 1;
    g_cluster[m] = cl;
    out[24576 + 32768 + m] = (float)cl;        // idx_cluster region (as float)
    atomicAdd(&g_allw[b * 2 + cl], g_tw[m]);
}

// ---------------- normalized weight output --------------------------------------
__global__ void weight_kernel(float* __restrict__ out) {
    int m = blockIdx.x * 256 + threadIdx.x;
    if (m >= NTOK) return;
    int b = m >> 11;
    float nw = g_tw[m] / g_allw[b * 2 + g_cluster[m]];
    out[24576 + m] = nw;                        // agg_weight_new region
}

// ---------------- weighted merge x_merged[b,k,:] ---------------------------------
__global__ __launch_bounds__(256) void merge_kernel(float* __restrict__ out) {
    __shared__ float wgt[NN];
    const int k = blockIdx.y, b = blockIdx.z;
    const int tid = threadIdx.x;
    const int c = blockIdx.x * 256 + tid;
    const float aw = g_allw[b * 2 + k];
    const int*   cl = g_cluster + b * NN;
    const float* tw = g_tw + b * NN;
    for (int j = tid; j < NN; j += 256)
        wgt[j] = (cl[j] == k) ? (tw[j] / aw) : 0.0f;
    __syncthreads();
    const float* xb = g_y + (size_t)b * NN * CC;
    float acc = 0.f;
    for (int n = 0; n < NN; ++n)
        acc = fmaf(xb[(size_t)n * CC + c], wgt[n], acc);
    out[(size_t)(b * 2 + k) * CC + c] = acc;    // x_merged region
}

// ---------------- launch --------------------------------------------------------
extern "C" void kernel_launch(void* const* d_in, const int* in_sizes, int n_in,
                              void* d_out, int out_size) {
    const float* x      = (const float*)d_in[0];
    const float* conv_w = (const float*)d_in[1];
    const float* gamma  = (const float*)d_in[2];
    const float* beta   = (const float*)d_in[3];
    const float* sw     = (const float*)d_in[4];
    const float* sb     = (const float*)d_in[5];
    const float* noise  = (const float*)d_in[6];
    float* out = (float*)d_out;

    cudaFuncSetAttribute(conv_mma_kernel, cudaFuncAttributeMaxDynamicSharedMemorySize, GEMM_SMEM);
    cudaFuncSetAttribute(gram_mma_kernel, cudaFuncAttributeMaxDynamicSharedMemorySize, GEMM_SMEM);

    repack_kernel<<<(CC * CC * 3 + 255) / 256, 256>>>(conv_w);
    prep_x_kernel<<<(NTOK * CC / 8) / 256, 256>>>(x);
    init_kernel<<<1, 32>>>();
    conv_mma_kernel<<<dim3(CC / 128, NTOK / 128), 256, GEMM_SMEM>>>(x);
    ln_kernel<<<NTOK, 256>>>(gamma, beta, sw, sb);
    gram_mma_kernel<<<dim3(136, 1, BB), 256, GEMM_SMEM>>>();
    knn_kernel<<<NTOK, 256>>>(noise);
    distmin_kernel<<<NTOK, 256>>>();
    top2_kernel<<<BB, 256>>>();
    assign_kernel<<<NTOK / 256, 256>>>(out);
    weight_kernel<<<NTOK / 256, 256>>>(out);
    merge_kernel<<<dim3(CC / 256, 2, BB), 256>>>(out);
}